// round 6
// baseline (speedup 1.0000x reference)
#include <cuda_runtime.h>
#include <stdint.h>
#include <math.h>

#define BB 8
#define CC 64
#define HH 256
#define WW 256
#define OHH 131
#define OWW 131
#define PP (OHH*OWW)      /* 17161 */
#define PSTR 17164        /* padded channel stride (multiple of 4) */
#define HWSZ (HH*WW)      /* 65536 */

// db4 filters
__constant__ float DEC_LO[8] = {
    -0.010597401784997278f, 0.032883011666982945f, 0.030841381835986965f,
    -0.18703481171888114f, -0.02798376941698385f, 0.6308807679295904f,
    0.7148465705525415f, 0.23037781330885523f };
__constant__ float DEC_HI[8] = {
    -0.23037781330885523f, 0.7148465705525415f, -0.6308807679295904f,
    -0.02798376941698385f, 0.18703481171888114f, 0.030841381835986965f,
    -0.032883011666982945f, -0.010597401784997278f };

// Scratch (device globals; allocation-free rule)
__device__ float g_ff[(size_t)BB*256*PSTR];    // ff then gated coeffs, (b, q=k*64+c, p)
__device__ float g_z[(size_t)BB*128*PSTR];     // z pre-GN, (b, o, p)
__device__ float g_recon[(size_t)BB*64*HWSZ];  // (b, c, h, w)
__device__ float g_stats[128];                 // (b,g): sum, sumsq
__device__ float g_density[512];               // raw nonzero counts (float)
__device__ float g_munorm[128];                // (b,g): mu, rsig
__device__ float g_gates[32];                  // (b, k)

// ---- tf32 helpers ----
__device__ __forceinline__ uint32_t f2tf32(float x) {
    uint32_t r; asm("cvt.rna.tf32.f32 %0, %1;" : "=r"(r) : "f"(x)); return r;
}
__device__ __forceinline__ void mma_tf32(float4& d, const uint32_t a[4], const uint32_t b[2]) {
    asm volatile("mma.sync.aligned.m16n8k8.row.col.f32.tf32.tf32.f32 "
        "{%0,%1,%2,%3}, {%4,%5,%6,%7}, {%8,%9}, {%0,%1,%2,%3};"
        : "+f"(d.x), "+f"(d.y), "+f"(d.z), "+f"(d.w)
        : "r"(a[0]), "r"(a[1]), "r"(a[2]), "r"(a[3]), "r"(b[0]), "r"(b[1]));
}
__device__ __forceinline__ uint4 tf4(float4 v) {
    uint4 u; u.x = f2tf32(v.x); u.y = f2tf32(v.y); u.z = f2tf32(v.z); u.w = f2tf32(v.w);
    return u;
}

// ---------------- K0: zero accumulators ----------------
__global__ void k_zero() {
    int t = threadIdx.x;             // 512 threads
    g_density[t] = 0.f;
    if (t < 128) g_stats[t] = 0.f;
}

// ---------------- K2: DWT2 -> g_ff (full-width row bands) + density count ----------------
// block = (hband 0..16, bc). 8 output rows x 131 cols per block.
// sIn col layout: orig col n lives at index n+8 (reflect-filled edges).
__global__ void __launch_bounds__(256) k_dwt(const float* __restrict__ x) {
    const int gi0 = blockIdx.x * 8;
    const int bc = blockIdx.y;
    __shared__ float sIn[22][272];
    __shared__ float sT[2][22][132];
    const float* xp = x + (size_t)bc * HWSZ;

    for (int idx = threadIdx.x; idx < 22 * 64; idx += 256) {
        int r = idx >> 6, q = idx & 63;
        int m = 2 * gi0 - 6 + r;
        m = (m < 0) ? (-1 - m) : ((m > 255) ? (511 - m) : m);
        float4 v = *(const float4*)&xp[m * 256 + 4 * q];
        *(float4*)&sIn[r][8 + 4 * q] = v;
    }
    for (int idx = threadIdx.x; idx < 22 * 12; idx += 256) {
        int r = idx / 12, e = idx % 12;
        int m = 2 * gi0 - 6 + r;
        m = (m < 0) ? (-1 - m) : ((m > 255) ? (511 - m) : m);
        int col = (e < 6) ? (2 + e) : (258 + e);
        int n = (e < 6) ? (5 - e) : (261 - e);
        sIn[r][col] = xp[m * 256 + n];
    }
    __syncthreads();
    // density: band b<16 uniquely owns orig rows 2*gi0..2*gi0+15 == sIn rows 6..21
    if (blockIdx.x < 16) {
        int cnt = 0;
        for (int idx = threadIdx.x; idx < 16 * 64; idx += 256) {
            int r = 6 + (idx >> 6), q = idx & 63;
            float4 v = *(const float4*)&sIn[r][8 + 4 * q];
            cnt += (v.x != 0.f) + (v.y != 0.f) + (v.z != 0.f) + (v.w != 0.f);
        }
        #pragma unroll
        for (int off = 16; off > 0; off >>= 1)
            cnt += __shfl_down_sync(0xffffffffu, cnt, off);
        __shared__ int swred[8];
        if ((threadIdx.x & 31) == 0) swred[threadIdx.x >> 5] = cnt;
        __syncthreads();
        if (threadIdx.x == 0) {
            int tot = 0;
            #pragma unroll
            for (int i = 0; i < 8; i++) tot += swred[i];
            atomicAdd(&g_density[bc], (float)tot);
        }
    }
    // row pass: 22 rows x 131 cols
    for (int idx = threadIdx.x; idx < 22 * 131; idx += 256) {
        int r = idx / 131, j = idx % 131;
        float lo = 0.f, hi = 0.f;
        #pragma unroll
        for (int v = 0; v < 8; v++) {
            float xv = sIn[r][2 * j + v + 2];
            lo += xv * DEC_LO[7 - v];
            hi += xv * DEC_HI[7 - v];
        }
        sT[0][r][j] = lo; sT[1][r][j] = hi;
    }
    __syncthreads();
    int b = bc >> 6, c = bc & 63;
    float* base = g_ff + ((size_t)b * 256 + c) * PSTR;
    for (int idx = threadIdx.x; idx < 8 * 131; idx += 256) {
        int ii = idx / 131, j = idx % 131;
        int gi = gi0 + ii;
        if (gi < OHH) {
            float aa = 0.f, da = 0.f, ad = 0.f, dd = 0.f;
            #pragma unroll
            for (int u = 0; u < 8; u++) {
                float tl = sT[0][2 * ii + u][j], th = sT[1][2 * ii + u][j];
                float gl = DEC_LO[7 - u], gh = DEC_HI[7 - u];
                aa += gl * tl; da += gh * tl; ad += gl * th; dd += gh * th;
            }
            int p = gi * OWW + j;
            base[p] = aa;
            base[(size_t)64 * PSTR + p] = da;
            base[(size_t)128 * PSTR + p] = ad;
            base[(size_t)192 * PSTR + p] = dd;
        }
    }
}

// ---------------- K3: z = ff @ w1^T + b1, + GN stats (tf32 tensor, pipelined) ----------------
__global__ void __launch_bounds__(256) k_gemm1(const float* __restrict__ w1,
                                               const float* __restrict__ b1) {
    const int b = blockIdx.y;
    const int p0 = blockIdx.x * 128;
    __shared__ uint32_t sW[2][128][20];
    __shared__ uint32_t sA[2][16][136];
    const int tid = threadIdx.x;
    const int w = tid >> 5, lane = tid & 31;
    const int gid = lane >> 2, tig = lane & 3;
    const int obase = (w >> 1) * 32, pbase = (w & 1) * 64;
    float4 acc[2][8] = {};
    const float* ffb = g_ff + (size_t)b * 256 * PSTR;
    const bool fullA = (p0 + 128 <= PP);

    const int ar0 = tid >> 5, ac0 = (tid & 31) * 4;
    const int wo0 = tid >> 2, wq0 = (tid & 3) * 4;
    float4 ra0, ra1, rw0, rw1;

    #define G1_LOAD(qc) do { \
        if (fullA) { \
            ra0 = *(const float4*)&ffb[(size_t)((qc) + ar0) * PSTR + p0 + ac0]; \
            ra1 = *(const float4*)&ffb[(size_t)((qc) + ar0 + 8) * PSTR + p0 + ac0]; \
        } else { \
            const float* r0p = &ffb[(size_t)((qc) + ar0) * PSTR]; \
            const float* r1p = &ffb[(size_t)((qc) + ar0 + 8) * PSTR]; \
            ra0.x = (p0+ac0   < PP) ? r0p[p0+ac0]   : 0.f; \
            ra0.y = (p0+ac0+1 < PP) ? r0p[p0+ac0+1] : 0.f; \
            ra0.z = (p0+ac0+2 < PP) ? r0p[p0+ac0+2] : 0.f; \
            ra0.w = (p0+ac0+3 < PP) ? r0p[p0+ac0+3] : 0.f; \
            ra1.x = (p0+ac0   < PP) ? r1p[p0+ac0]   : 0.f; \
            ra1.y = (p0+ac0+1 < PP) ? r1p[p0+ac0+1] : 0.f; \
            ra1.z = (p0+ac0+2 < PP) ? r1p[p0+ac0+2] : 0.f; \
            ra1.w = (p0+ac0+3 < PP) ? r1p[p0+ac0+3] : 0.f; \
        } \
        rw0 = *(const float4*)&w1[wo0 * 256 + (qc) + wq0]; \
        rw1 = *(const float4*)&w1[(wo0 + 64) * 256 + (qc) + wq0]; \
    } while (0)
    #define G1_STORE(st) do { \
        *(uint4*)&sA[st][ar0][ac0]     = tf4(ra0); \
        *(uint4*)&sA[st][ar0 + 8][ac0] = tf4(ra1); \
        *(uint4*)&sW[st][wo0][wq0]       = tf4(rw0); \
        *(uint4*)&sW[st][wo0 + 64][wq0]  = tf4(rw1); \
    } while (0)

    G1_LOAD(0); G1_STORE(0);
    __syncthreads();
    int cur = 0;
    for (int qc = 0; qc < 256; qc += 16) {
        const bool hasnext = (qc + 16 < 256);
        if (hasnext) G1_LOAD(qc + 16);
        #pragma unroll
        for (int ks = 0; ks < 2; ks++) {
            int k0 = ks * 8;
            uint32_t afr[2][4];
            #pragma unroll
            for (int mt = 0; mt < 2; mt++) {
                int o = obase + mt * 16 + gid;
                afr[mt][0] = sW[cur][o][k0 + tig];
                afr[mt][1] = sW[cur][o + 8][k0 + tig];
                afr[mt][2] = sW[cur][o][k0 + tig + 4];
                afr[mt][3] = sW[cur][o + 8][k0 + tig + 4];
            }
            #pragma unroll
            for (int nt = 0; nt < 8; nt++) {
                uint32_t bfr[2];
                int p = pbase + nt * 8 + gid;
                bfr[0] = sA[cur][k0 + tig][p];
                bfr[1] = sA[cur][k0 + tig + 4][p];
                mma_tf32(acc[0][nt], afr[0], bfr);
                mma_tf32(acc[1][nt], afr[1], bfr);
            }
        }
        if (hasnext) G1_STORE(cur ^ 1);
        __syncthreads();
        cur ^= 1;
    }
    float s1[2] = {0.f, 0.f}, s2[2] = {0.f, 0.f};
    float* zb = g_z + (size_t)b * 128 * PSTR;
    #pragma unroll
    for (int mt = 0; mt < 2; mt++) {
        int o1 = obase + mt * 16 + gid;
        float bia = b1[o1], bib = b1[o1 + 8];
        #pragma unroll
        for (int nt = 0; nt < 8; nt++) {
            int p = p0 + pbase + nt * 8 + 2 * tig;
            float vx = acc[mt][nt].x + bia, vy = acc[mt][nt].y + bia;
            float vz = acc[mt][nt].z + bib, vw = acc[mt][nt].w + bib;
            if (fullA) {
                s1[mt] += vx + vy + vz + vw;
                s2[mt] += vx*vx + vy*vy + vz*vz + vw*vw;
                *(float2*)&zb[(size_t)o1 * PSTR + p] = make_float2(vx, vy);
                *(float2*)&zb[(size_t)(o1 + 8) * PSTR + p] = make_float2(vz, vw);
            } else {
                if (p < PP)     { zb[(size_t)o1*PSTR + p] = vx;       zb[(size_t)(o1+8)*PSTR + p] = vz;       s1[mt] += vx + vz; s2[mt] += vx*vx + vz*vz; }
                if (p + 1 < PP) { zb[(size_t)o1*PSTR + p + 1] = vy;   zb[(size_t)(o1+8)*PSTR + p + 1] = vw;   s1[mt] += vy + vw; s2[mt] += vy*vy + vw*vw; }
            }
        }
    }
    #pragma unroll
    for (int off = 16; off > 0; off >>= 1) {
        s1[0] += __shfl_down_sync(0xffffffffu, s1[0], off);
        s2[0] += __shfl_down_sync(0xffffffffu, s2[0], off);
        s1[1] += __shfl_down_sync(0xffffffffu, s1[1], off);
        s2[1] += __shfl_down_sync(0xffffffffu, s2[1], off);
    }
    if (lane == 0) {
        int g0 = (w >> 1) * 2;
        atomicAdd(&g_stats[(b * 8 + g0) * 2],     s1[0]);
        atomicAdd(&g_stats[(b * 8 + g0) * 2 + 1], s2[0]);
        atomicAdd(&g_stats[(b * 8 + g0 + 1) * 2],     s1[1]);
        atomicAdd(&g_stats[(b * 8 + g0 + 1) * 2 + 1], s2[1]);
    }
}

// ---------------- K4: finalize stats + gates (warp-parallel) ----------------
__global__ void k_small(const float* __restrict__ g1, const float* __restrict__ gb1,
                        const float* __restrict__ g2, const float* __restrict__ gb2) {
    int t = threadIdx.x;
    if (t < 64) {
        float s1 = g_stats[2 * t], s2 = g_stats[2 * t + 1];
        float invN = 1.f / (16.f * (float)PP);
        float mu = s1 * invN;
        float var = s2 * invN - mu * mu;
        g_munorm[2 * t] = mu;
        g_munorm[2 * t + 1] = rsqrtf(var + 1e-5f);
    }
    __shared__ float sh[8][16];
    int w = t >> 5, lane = t & 31;
    const float invHW = 1.f / (float)HWSZ;
    if (lane < 16) {
        float s = gb1[lane];
        #pragma unroll 4
        for (int c = 0; c < 64; c++) s += (g_density[w * 64 + c] * invHW) * g1[lane * 64 + c];
        sh[w][lane] = fmaxf(s, 0.f);
    }
    __syncwarp();
    if (lane < 4) {
        float s = gb2[lane];
        #pragma unroll
        for (int i = 0; i < 16; i++) s += sh[w][i] * g2[lane * 16 + i];
        g_gates[w * 4 + lane] = 1.f / (1.f + expf(-s));
    }
}

// ---------------- K5: gated = (gelu(GN(z)) @ w2^T + b2) * gate ----------------
__global__ void __launch_bounds__(256) k_gemm2(const float* __restrict__ w2,
                                               const float* __restrict__ b2,
                                               const float* __restrict__ gamma,
                                               const float* __restrict__ beta) {
    const int b = blockIdx.y;
    const int p0 = blockIdx.x * 64;
    __shared__ uint32_t sWt[2][16][260];   // K-major W tile
    __shared__ uint32_t sA[2][16][72];
    __shared__ float sScale[128], sShift[128];
    const int tid = threadIdx.x;
    if (tid < 128) {
        int q = tid, g = q >> 4;
        float mu = g_munorm[(b * 8 + g) * 2];
        float rs = g_munorm[(b * 8 + g) * 2 + 1];
        float sc = rs * gamma[q];
        sScale[q] = sc;
        sShift[q] = beta[q] - mu * sc;
    }
    __syncthreads();
    const int w = tid >> 5, lane = tid & 31;
    const int gid = lane >> 2, tig = lane & 3;
    const int obase = (w >> 1) * 64, pbase = (w & 1) * 32;
    float4 acc[4][4] = {};
    const float* zb = g_z + (size_t)b * 128 * PSTR;
    const bool fullA = (p0 + 64 <= PP);

    const int ar = tid >> 4, ac = (tid & 15) * 4;
    const int wo = tid >> 2, wq = (tid & 3) * 4;
    float4 ra, rw[4];

    #define G2_LOAD(qc) do { \
        if (fullA) { \
            ra = *(const float4*)&zb[(size_t)((qc) + ar) * PSTR + p0 + ac]; \
        } else { \
            const float* rp = &zb[(size_t)((qc) + ar) * PSTR]; \
            ra.x = (p0+ac   < PP) ? rp[p0+ac]   : 0.f; \
            ra.y = (p0+ac+1 < PP) ? rp[p0+ac+1] : 0.f; \
            ra.z = (p0+ac+2 < PP) ? rp[p0+ac+2] : 0.f; \
            ra.w = (p0+ac+3 < PP) ? rp[p0+ac+3] : 0.f; \
        } \
        _Pragma("unroll") \
        for (int s = 0; s < 4; s++) \
            rw[s] = *(const float4*)&w2[(wo + s * 64) * 128 + (qc) + wq]; \
    } while (0)
    #define GELU4(v, row) do { \
        float sc_ = sScale[row], sh_ = sShift[row]; \
        v.x = v.x * sc_ + sh_; v.x = 0.5f * v.x * (1.f + erff(v.x * 0.70710678118654752f)); \
        v.y = v.y * sc_ + sh_; v.y = 0.5f * v.y * (1.f + erff(v.y * 0.70710678118654752f)); \
        v.z = v.z * sc_ + sh_; v.z = 0.5f * v.z * (1.f + erff(v.z * 0.70710678118654752f)); \
        v.w = v.w * sc_ + sh_; v.w = 0.5f * v.w * (1.f + erff(v.w * 0.70710678118654752f)); \
    } while (0)
    #define G2_STORE(st, qc) do { \
        GELU4(ra, (qc) + ar); \
        *(uint4*)&sA[st][ar][ac] = tf4(ra); \
        _Pragma("unroll") \
        for (int s = 0; s < 4; s++) { \
            sWt[st][wq + 0][wo + s * 64] = f2tf32(rw[s].x); \
            sWt[st][wq + 1][wo + s * 64] = f2tf32(rw[s].y); \
            sWt[st][wq + 2][wo + s * 64] = f2tf32(rw[s].z); \
            sWt[st][wq + 3][wo + s * 64] = f2tf32(rw[s].w); \
        } \
    } while (0)

    G2_LOAD(0); G2_STORE(0, 0);
    __syncthreads();
    int cur = 0;
    for (int qc = 0; qc < 128; qc += 16) {
        const bool hasnext = (qc + 16 < 128);
        if (hasnext) G2_LOAD(qc + 16);
        #pragma unroll
        for (int ks = 0; ks < 2; ks++) {
            int k0 = ks * 8;
            uint32_t afr[4][4];
            #pragma unroll
            for (int mt = 0; mt < 4; mt++) {
                int o = obase + mt * 16 + gid;
                afr[mt][0] = sWt[cur][k0 + tig][o];
                afr[mt][1] = sWt[cur][k0 + tig][o + 8];
                afr[mt][2] = sWt[cur][k0 + tig + 4][o];
                afr[mt][3] = sWt[cur][k0 + tig + 4][o + 8];
            }
            #pragma unroll
            for (int nt = 0; nt < 4; nt++) {
                uint32_t bfr[2];
                int p = pbase + nt * 8 + gid;
                bfr[0] = sA[cur][k0 + tig][p];
                bfr[1] = sA[cur][k0 + tig + 4][p];
                #pragma unroll
                for (int mt = 0; mt < 4; mt++)
                    mma_tf32(acc[mt][nt], afr[mt], bfr);
            }
        }
        if (hasnext) G2_STORE(cur ^ 1, qc + 16);
        __syncthreads();
        cur ^= 1;
    }
    float* gbuf = g_ff + (size_t)b * 256 * PSTR;
    #pragma unroll
    for (int mt = 0; mt < 4; mt++) {
        int o1 = obase + mt * 16 + gid;
        float ga = g_gates[b * 4 + (o1 >> 6)];
        float gb_ = g_gates[b * 4 + ((o1 + 8) >> 6)];
        float bia = b2[o1], bib = b2[o1 + 8];
        #pragma unroll
        for (int nt = 0; nt < 4; nt++) {
            int p = p0 + pbase + nt * 8 + 2 * tig;
            float vx = (acc[mt][nt].x + bia) * ga, vy = (acc[mt][nt].y + bia) * ga;
            float vz = (acc[mt][nt].z + bib) * gb_, vw = (acc[mt][nt].w + bib) * gb_;
            if (fullA) {
                *(float2*)&gbuf[(size_t)o1 * PSTR + p] = make_float2(vx, vy);
                *(float2*)&gbuf[(size_t)(o1 + 8) * PSTR + p] = make_float2(vz, vw);
            } else {
                if (p < PP)     { gbuf[(size_t)o1*PSTR + p] = vx;     gbuf[(size_t)(o1+8)*PSTR + p] = vz; }
                if (p + 1 < PP) { gbuf[(size_t)o1*PSTR + p + 1] = vy; gbuf[(size_t)(o1+8)*PSTR + p + 1] = vw; }
            }
        }
    }
}

// ---------------- K6: IDWT2 -> g_recon (full-width h-bands) ----------------
// block = (hband 0..31, bc). 8 output rows x 256 cols.
__global__ void __launch_bounds__(256) k_idwt() {
    const int h0 = blockIdx.x * 8;
    const int bc = blockIdx.y;
    const int b = bc >> 6, c = bc & 63;
    __shared__ float scoef[4][7][132];
    __shared__ float stmp[4][7][260];
    const float* gb = g_ff + ((size_t)b * 256 + c) * PSTR;
    const int ib0 = h0 >> 1;

    // load 4 subbands x 7 coeff rows x 131 cols (contiguous per row)
    for (int idx = threadIdx.x; idx < 4 * 7 * 131; idx += 256) {
        int k = idx / (7 * 131); int rem = idx % (7 * 131);
        int il = rem / 131, j = rem % 131;
        scoef[k][il][j] = gb[(size_t)k * 64 * PSTR + (ib0 + il) * OWW + j];
    }
    __syncthreads();
    // pass1: w synthesis. each thread handles (il, jb) -> outputs wl=2jb, 2jb+1 for all 4 k.
    for (int s = threadIdx.x; s < 7 * 128; s += 256) {
        int il = s >> 7, jb = s & 127;
        int wl = jb * 2;
        #pragma unroll
        for (int k = 0; k < 4; k++) {
            const float* fc = (k < 2) ? DEC_LO : DEC_HI;
            float c0 = scoef[k][il][jb],     c1 = scoef[k][il][jb + 1];
            float c2 = scoef[k][il][jb + 2], c3 = scoef[k][il][jb + 3];
            stmp[k][il][wl]     = c0*fc[1] + c1*fc[3] + c2*fc[5] + c3*fc[7];
            stmp[k][il][wl + 1] = c0*fc[0] + c1*fc[2] + c2*fc[4] + c3*fc[6];
        }
    }
    __syncthreads();
    // pass2: h synthesis. 8 rows x 256 cols.
    float* rb = g_recon + ((size_t)b * 64 + c) * HWSZ;
    for (int s = threadIdx.x; s < 8 * 256; s += 256) {
        int wl = s & 255, dh = s >> 8;
        int sh = dh >> 1;
        float acc = 0.f;
        #pragma unroll
        for (int k = 0; k < 4; k++) {
            const float* fr = (k & 1) ? DEC_HI : DEC_LO;
            float t0 = stmp[k][sh][wl],     t1 = stmp[k][sh + 1][wl];
            float t2 = stmp[k][sh + 2][wl], t3 = stmp[k][sh + 3][wl];
            if (dh & 1)
                acc += t0*fr[0] + t1*fr[2] + t2*fr[4] + t3*fr[6];
            else
                acc += t0*fr[1] + t1*fr[3] + t2*fr[5] + t3*fr[7];
        }
        rb[(h0 + dh) * WW + wl] = acc;
    }
}

// ---------------- K7: fused = [x, recon] @ wf^T + bf (tf32, pipelined) ----------------
__global__ void __launch_bounds__(256) k_final(const float* __restrict__ x,
                                               const float* __restrict__ wf,
                                               const float* __restrict__ bf,
                                               float* __restrict__ out) {
    const int b = blockIdx.y;
    const int p0 = blockIdx.x * 256;
    __shared__ uint32_t sW[2][64][20];
    __shared__ uint32_t sA[2][16][264];
    const int tid = threadIdx.x;
    const int w = tid >> 5, lane = tid & 31;
    const int gid = lane >> 2, tig = lane & 3;
    const int obase = (w >> 2) * 32, pbase = (w & 3) * 64;
    float4 acc[2][8] = {};
    const float* xb = x + (size_t)b * 64 * HWSZ;
    const float* rb = g_recon + (size_t)b * 64 * HWSZ;

    const int ar0 = tid >> 6;
    const int ac0 = (tid & 63) * 4;
    const int wo0 = tid >> 2, wq0 = (tid & 3) * 4;
    float4 ra[4], rw0;

    #define G3_LOAD(cc) do { \
        _Pragma("unroll") \
        for (int s = 0; s < 4; s++) { \
            int ch = (cc) + ar0 + s * 4; \
            const float* src = (ch < 64) ? &xb[(size_t)ch * HWSZ] : &rb[(size_t)(ch - 64) * HWSZ]; \
            ra[s] = *(const float4*)&src[p0 + ac0]; \
        } \
        rw0 = *(const float4*)&wf[wo0 * 128 + (cc) + wq0]; \
    } while (0)
    #define G3_STORE(st) do { \
        _Pragma("unroll") \
        for (int s = 0; s < 4; s++) \
            *(uint4*)&sA[st][ar0 + s * 4][ac0] = tf4(ra[s]); \
        *(uint4*)&sW[st][wo0][wq0] = tf4(rw0); \
    } while (0)

    G3_LOAD(0); G3_STORE(0);
    __syncthreads();
    int cur = 0;
    for (int cc = 0; cc < 128; cc += 16) {
        const bool hasnext = (cc + 16 < 128);
        if (hasnext) G3_LOAD(cc + 16);
        #pragma unroll
        for (int ks = 0; ks < 2; ks++) {
            int k0 = ks * 8;
            uint32_t afr[2][4];
            #pragma unroll
            for (int mt = 0; mt < 2; mt++) {
                int o = obase + mt * 16 + gid;
                afr[mt][0] = sW[cur][o][k0 + tig];
                afr[mt][1] = sW[cur][o + 8][k0 + tig];
                afr[mt][2] = sW[cur][o][k0 + tig + 4];
                afr[mt][3] = sW[cur][o + 8][k0 + tig + 4];
            }
            #pragma unroll
            for (int nt = 0; nt < 8; nt++) {
                uint32_t bfr[2];
                int p = pbase + nt * 8 + gid;
                bfr[0] = sA[cur][k0 + tig][p];
                bfr[1] = sA[cur][k0 + tig + 4][p];
                mma_tf32(acc[0][nt], afr[0], bfr);
                mma_tf32(acc[1][nt], afr[1], bfr);
            }
        }
        if (hasnext) G3_STORE(cur ^ 1);
        __syncthreads();
        cur ^= 1;
    }
    float* ob = out + (size_t)b * 64 * HWSZ;
    #pragma unroll
    for (int mt = 0; mt < 2; mt++) {
        int o1 = obase + mt * 16 + gid;
        float bia = bf[o1], bib = bf[o1 + 8];
        #pragma unroll
        for (int nt = 0; nt < 8; nt++) {
            int p = p0 + pbase + nt * 8 + 2 * tig;
            *(float2*)&ob[(size_t)o1 * HWSZ + p] = make_float2(acc[mt][nt].x + bia, acc[mt][nt].y + bia);
            *(float2*)&ob[(size_t)(o1 + 8) * HWSZ + p] = make_float2(acc[mt][nt].z + bib, acc[mt][nt].w + bib);
        }
    }
}

extern "C" void kernel_launch(void* const* d_in, const int* in_sizes, int n_in,
                              void* d_out, int out_size) {
    const float* x     = (const float*)d_in[0];
    const float* w1    = (const float*)d_in[1];
    const float* b1    = (const float*)d_in[2];
    const float* gamma = (const float*)d_in[3];
    const float* beta  = (const float*)d_in[4];
    const float* w2    = (const float*)d_in[5];
    const float* b2    = (const float*)d_in[6];
    const float* g1    = (const float*)d_in[7];
    const float* gb1   = (const float*)d_in[8];
    const float* g2    = (const float*)d_in[9];
    const float* gb2   = (const float*)d_in[10];
    const float* wf    = (const float*)d_in[11];
    const float* bf    = (const float*)d_in[12];
    float* out = (float*)d_out;

    k_zero<<<1, 512>>>();
    k_dwt<<<dim3(17, 512), 256>>>(x);
    k_gemm1<<<dim3(135, 8), 256>>>(w1, b1);
    k_small<<<1, 256>>>(g1, gb1, g2, gb2);
    k_gemm2<<<dim3(269, 8), 256>>>(w2, b2, gamma, beta);
    k_idwt<<<dim3(32, 512), 256>>>();
    k_final<<<dim3(256, 8), 256>>>(x, wf, bf, out);
}

// round 7
// speedup vs baseline: 1.0832x; 1.0832x over previous
#include <cuda_runtime.h>
#include <stdint.h>
#include <math.h>

#define BB 8
#define CC 64
#define HH 256
#define WW 256
#define OHH 131
#define OWW 131
#define PP (OHH*OWW)      /* 17161 */
#define PSTR 17164        /* padded channel stride (multiple of 4) */
#define HWSZ (HH*WW)      /* 65536 */

// db4 filters
__constant__ float DEC_LO[8] = {
    -0.010597401784997278f, 0.032883011666982945f, 0.030841381835986965f,
    -0.18703481171888114f, -0.02798376941698385f, 0.6308807679295904f,
    0.7148465705525415f, 0.23037781330885523f };
__constant__ float DEC_HI[8] = {
    -0.23037781330885523f, 0.7148465705525415f, -0.6308807679295904f,
    -0.02798376941698385f, 0.18703481171888114f, 0.030841381835986965f,
    -0.032883011666982945f, -0.010597401784997278f };

// Scratch (device globals; allocation-free rule)
__device__ float g_ff[(size_t)BB*256*PSTR];    // ff then gated coeffs, (b, q=k*64+c, p)
__device__ float g_z[(size_t)BB*128*PSTR];     // z pre-GN, (b, o, p)
__device__ float g_recon[(size_t)BB*64*HWSZ];  // (b, c, h, w)
__device__ float g_stats[128];                 // (b,g): sum, sumsq
__device__ float g_density[512];
__device__ float g_munorm[128];                // (b,g): mu, rsig
__device__ float g_gates[32];                  // (b, k)

// ---- tf32 helpers ----
__device__ __forceinline__ uint32_t f2tf32(float x) {
    uint32_t r; asm("cvt.rna.tf32.f32 %0, %1;" : "=r"(r) : "f"(x)); return r;
}
__device__ __forceinline__ void mma_tf32(float4& d, const uint32_t a[4], const uint32_t b[2]) {
    asm volatile("mma.sync.aligned.m16n8k8.row.col.f32.tf32.tf32.f32 "
        "{%0,%1,%2,%3}, {%4,%5,%6,%7}, {%8,%9}, {%0,%1,%2,%3};"
        : "+f"(d.x), "+f"(d.y), "+f"(d.z), "+f"(d.w)
        : "r"(a[0]), "r"(a[1]), "r"(a[2]), "r"(a[3]), "r"(b[0]), "r"(b[1]));
}
__device__ __forceinline__ uint4 tf4(float4 v) {
    uint4 u; u.x = f2tf32(v.x); u.y = f2tf32(v.y); u.z = f2tf32(v.z); u.w = f2tf32(v.w);
    return u;
}

// ---------------- K1: density (half range per launch) + zero stats ----------------
__global__ void k_density(const float* __restrict__ x, int base) {
    int bc = base + blockIdx.x;
    const float4* xp = (const float4*)(x + (size_t)bc * HWSZ);
    int cnt = 0;
    for (int i = threadIdx.x; i < HWSZ/4; i += 256) {
        float4 v = xp[i];
        cnt += (v.x != 0.f) + (v.y != 0.f) + (v.z != 0.f) + (v.w != 0.f);
    }
    #pragma unroll
    for (int off = 16; off > 0; off >>= 1)
        cnt += __shfl_down_sync(0xffffffffu, cnt, off);
    __shared__ int swred[8];
    if ((threadIdx.x & 31) == 0) swred[threadIdx.x >> 5] = cnt;
    __syncthreads();
    if (threadIdx.x == 0) {
        int tot = 0;
        #pragma unroll
        for (int i = 0; i < 8; i++) tot += swred[i];
        g_density[bc] = (float)tot / (float)HWSZ;
    }
    if (base == 0 && blockIdx.x == 0 && threadIdx.x < 128) g_stats[threadIdx.x] = 0.f;
}

// ---------------- K2: DWT2 -> g_ff (full-width row bands) ----------------
__global__ void __launch_bounds__(256) k_dwt(const float* __restrict__ x) {
    const int gi0 = blockIdx.x * 8;
    const int bc = blockIdx.y;
    __shared__ float sIn[22][272];
    __shared__ float sT[2][22][132];
    const float* xp = x + (size_t)bc * HWSZ;

    for (int idx = threadIdx.x; idx < 22 * 64; idx += 256) {
        int r = idx >> 6, q = idx & 63;
        int m = 2 * gi0 - 6 + r;
        m = (m < 0) ? (-1 - m) : ((m > 255) ? (511 - m) : m);
        float4 v = *(const float4*)&xp[m * 256 + 4 * q];
        *(float4*)&sIn[r][8 + 4 * q] = v;
    }
    for (int idx = threadIdx.x; idx < 22 * 12; idx += 256) {
        int r = idx / 12, e = idx % 12;
        int m = 2 * gi0 - 6 + r;
        m = (m < 0) ? (-1 - m) : ((m > 255) ? (511 - m) : m);
        int col = (e < 6) ? (2 + e) : (258 + e);
        int n = (e < 6) ? (5 - e) : (261 - e);
        sIn[r][col] = xp[m * 256 + n];
    }
    __syncthreads();
    for (int idx = threadIdx.x; idx < 22 * 131; idx += 256) {
        int r = idx / 131, j = idx % 131;
        float lo = 0.f, hi = 0.f;
        #pragma unroll
        for (int v = 0; v < 8; v++) {
            float xv = sIn[r][2 * j + v + 2];
            lo += xv * DEC_LO[7 - v];
            hi += xv * DEC_HI[7 - v];
        }
        sT[0][r][j] = lo; sT[1][r][j] = hi;
    }
    __syncthreads();
    int b = bc >> 6, c = bc & 63;
    float* base = g_ff + ((size_t)b * 256 + c) * PSTR;
    for (int idx = threadIdx.x; idx < 8 * 131; idx += 256) {
        int ii = idx / 131, j = idx % 131;
        int gi = gi0 + ii;
        if (gi < OHH) {
            float aa = 0.f, da = 0.f, ad = 0.f, dd = 0.f;
            #pragma unroll
            for (int u = 0; u < 8; u++) {
                float tl = sT[0][2 * ii + u][j], th = sT[1][2 * ii + u][j];
                float gl = DEC_LO[7 - u], gh = DEC_HI[7 - u];
                aa += gl * tl; da += gh * tl; ad += gl * th; dd += gh * th;
            }
            int p = gi * OWW + j;
            base[p] = aa;
            base[(size_t)64 * PSTR + p] = da;
            base[(size_t)128 * PSTR + p] = ad;
            base[(size_t)192 * PSTR + p] = dd;
        }
    }
}

// ---------------- K3: z = ff @ w1^T + b1, + GN stats (tf32 tensor, pipelined) ----------------
__global__ void __launch_bounds__(256) k_gemm1(const float* __restrict__ w1,
                                               const float* __restrict__ b1) {
    const int b = blockIdx.y;
    const int p0 = blockIdx.x * 128;
    __shared__ uint32_t sW[2][128][20];
    __shared__ uint32_t sA[2][16][136];
    const int tid = threadIdx.x;
    const int w = tid >> 5, lane = tid & 31;
    const int gid = lane >> 2, tig = lane & 3;
    const int obase = (w >> 1) * 32, pbase = (w & 1) * 64;
    float4 acc[2][8] = {};
    const float* ffb = g_ff + (size_t)b * 256 * PSTR;
    const bool fullA = (p0 + 128 <= PP);

    const int ar0 = tid >> 5, ac0 = (tid & 31) * 4;
    const int wo0 = tid >> 2, wq0 = (tid & 3) * 4;
    float4 ra0, ra1, rw0, rw1;

    #define G1_LOAD(qc) do { \
        if (fullA) { \
            ra0 = *(const float4*)&ffb[(size_t)((qc) + ar0) * PSTR + p0 + ac0]; \
            ra1 = *(const float4*)&ffb[(size_t)((qc) + ar0 + 8) * PSTR + p0 + ac0]; \
        } else { \
            const float* r0p = &ffb[(size_t)((qc) + ar0) * PSTR]; \
            const float* r1p = &ffb[(size_t)((qc) + ar0 + 8) * PSTR]; \
            ra0.x = (p0+ac0   < PP) ? r0p[p0+ac0]   : 0.f; \
            ra0.y = (p0+ac0+1 < PP) ? r0p[p0+ac0+1] : 0.f; \
            ra0.z = (p0+ac0+2 < PP) ? r0p[p0+ac0+2] : 0.f; \
            ra0.w = (p0+ac0+3 < PP) ? r0p[p0+ac0+3] : 0.f; \
            ra1.x = (p0+ac0   < PP) ? r1p[p0+ac0]   : 0.f; \
            ra1.y = (p0+ac0+1 < PP) ? r1p[p0+ac0+1] : 0.f; \
            ra1.z = (p0+ac0+2 < PP) ? r1p[p0+ac0+2] : 0.f; \
            ra1.w = (p0+ac0+3 < PP) ? r1p[p0+ac0+3] : 0.f; \
        } \
        rw0 = *(const float4*)&w1[wo0 * 256 + (qc) + wq0]; \
        rw1 = *(const float4*)&w1[(wo0 + 64) * 256 + (qc) + wq0]; \
    } while (0)
    #define G1_STORE(st) do { \
        *(uint4*)&sA[st][ar0][ac0]     = tf4(ra0); \
        *(uint4*)&sA[st][ar0 + 8][ac0] = tf4(ra1); \
        *(uint4*)&sW[st][wo0][wq0]       = tf4(rw0); \
        *(uint4*)&sW[st][wo0 + 64][wq0]  = tf4(rw1); \
    } while (0)

    G1_LOAD(0); G1_STORE(0);
    __syncthreads();
    int cur = 0;
    for (int qc = 0; qc < 256; qc += 16) {
        const bool hasnext = (qc + 16 < 256);
        if (hasnext) G1_LOAD(qc + 16);
        #pragma unroll
        for (int ks = 0; ks < 2; ks++) {
            int k0 = ks * 8;
            uint32_t afr[2][4];
            #pragma unroll
            for (int mt = 0; mt < 2; mt++) {
                int o = obase + mt * 16 + gid;
                afr[mt][0] = sW[cur][o][k0 + tig];
                afr[mt][1] = sW[cur][o + 8][k0 + tig];
                afr[mt][2] = sW[cur][o][k0 + tig + 4];
                afr[mt][3] = sW[cur][o + 8][k0 + tig + 4];
            }
            #pragma unroll
            for (int nt = 0; nt < 8; nt++) {
                uint32_t bfr[2];
                int p = pbase + nt * 8 + gid;
                bfr[0] = sA[cur][k0 + tig][p];
                bfr[1] = sA[cur][k0 + tig + 4][p];
                mma_tf32(acc[0][nt], afr[0], bfr);
                mma_tf32(acc[1][nt], afr[1], bfr);
            }
        }
        if (hasnext) G1_STORE(cur ^ 1);
        __syncthreads();
        cur ^= 1;
    }
    float s1[2] = {0.f, 0.f}, s2[2] = {0.f, 0.f};
    float* zb = g_z + (size_t)b * 128 * PSTR;
    #pragma unroll
    for (int mt = 0; mt < 2; mt++) {
        int o1 = obase + mt * 16 + gid;
        float bia = b1[o1], bib = b1[o1 + 8];
        #pragma unroll
        for (int nt = 0; nt < 8; nt++) {
            int p = p0 + pbase + nt * 8 + 2 * tig;
            float vx = acc[mt][nt].x + bia, vy = acc[mt][nt].y + bia;
            float vz = acc[mt][nt].z + bib, vw = acc[mt][nt].w + bib;
            if (fullA) {
                s1[mt] += vx + vy + vz + vw;
                s2[mt] += vx*vx + vy*vy + vz*vz + vw*vw;
                *(float2*)&zb[(size_t)o1 * PSTR + p] = make_float2(vx, vy);
                *(float2*)&zb[(size_t)(o1 + 8) * PSTR + p] = make_float2(vz, vw);
            } else {
                if (p < PP)     { zb[(size_t)o1*PSTR + p] = vx;       zb[(size_t)(o1+8)*PSTR + p] = vz;       s1[mt] += vx + vz; s2[mt] += vx*vx + vz*vz; }
                if (p + 1 < PP) { zb[(size_t)o1*PSTR + p + 1] = vy;   zb[(size_t)(o1+8)*PSTR + p + 1] = vw;   s1[mt] += vy + vw; s2[mt] += vy*vy + vw*vw; }
            }
        }
    }
    #pragma unroll
    for (int off = 16; off > 0; off >>= 1) {
        s1[0] += __shfl_down_sync(0xffffffffu, s1[0], off);
        s2[0] += __shfl_down_sync(0xffffffffu, s2[0], off);
        s1[1] += __shfl_down_sync(0xffffffffu, s1[1], off);
        s2[1] += __shfl_down_sync(0xffffffffu, s2[1], off);
    }
    if (lane == 0) {
        int g0 = (w >> 1) * 2;
        atomicAdd(&g_stats[(b * 8 + g0) * 2],     s1[0]);
        atomicAdd(&g_stats[(b * 8 + g0) * 2 + 1], s2[0]);
        atomicAdd(&g_stats[(b * 8 + g0 + 1) * 2],     s1[1]);
        atomicAdd(&g_stats[(b * 8 + g0 + 1) * 2 + 1], s2[1]);
    }
}

// ---------------- K4: finalize stats + gates (warp-parallel) ----------------
__global__ void k_small(const float* __restrict__ g1, const float* __restrict__ gb1,
                        const float* __restrict__ g2, const float* __restrict__ gb2) {
    int t = threadIdx.x;
    if (t < 64) {
        float s1 = g_stats[2 * t], s2 = g_stats[2 * t + 1];
        float invN = 1.f / (16.f * (float)PP);
        float mu = s1 * invN;
        float var = s2 * invN - mu * mu;
        g_munorm[2 * t] = mu;
        g_munorm[2 * t + 1] = rsqrtf(var + 1e-5f);
    }
    __shared__ float sh[8][16];
    int w = t >> 5, lane = t & 31;
    if (lane < 16) {
        float s = gb1[lane];
        #pragma unroll 4
        for (int c = 0; c < 64; c++) s += g_density[w * 64 + c] * g1[lane * 64 + c];
        sh[w][lane] = fmaxf(s, 0.f);
    }
    __syncwarp();
    if (lane < 4) {
        float s = gb2[lane];
        #pragma unroll
        for (int i = 0; i < 16; i++) s += sh[w][i] * g2[lane * 16 + i];
        g_gates[w * 4 + lane] = 1.f / (1.f + expf(-s));
    }
}

// ---------------- K5: gated = (gelu(GN(z)) @ w2^T + b2) * gate ----------------
__global__ void __launch_bounds__(256) k_gemm2(const float* __restrict__ w2,
                                               const float* __restrict__ b2,
                                               const float* __restrict__ gamma,
                                               const float* __restrict__ beta) {
    const int b = blockIdx.y;
    const int p0 = blockIdx.x * 64;
    __shared__ uint32_t sWt[2][16][260];   // K-major W tile
    __shared__ uint32_t sA[2][16][72];
    __shared__ float sScale[128], sShift[128];
    const int tid = threadIdx.x;
    if (tid < 128) {
        int q = tid, g = q >> 4;
        float mu = g_munorm[(b * 8 + g) * 2];
        float rs = g_munorm[(b * 8 + g) * 2 + 1];
        float sc = rs * gamma[q];
        sScale[q] = sc;
        sShift[q] = beta[q] - mu * sc;
    }
    __syncthreads();
    const int w = tid >> 5, lane = tid & 31;
    const int gid = lane >> 2, tig = lane & 3;
    const int obase = (w >> 1) * 64, pbase = (w & 1) * 32;
    float4 acc[4][4] = {};
    const float* zb = g_z + (size_t)b * 128 * PSTR;
    const bool fullA = (p0 + 64 <= PP);

    const int ar = tid >> 4, ac = (tid & 15) * 4;
    const int wo = tid >> 2, wq = (tid & 3) * 4;
    float4 ra, rw[4];

    #define G2_LOAD(qc) do { \
        if (fullA) { \
            ra = *(const float4*)&zb[(size_t)((qc) + ar) * PSTR + p0 + ac]; \
        } else { \
            const float* rp = &zb[(size_t)((qc) + ar) * PSTR]; \
            ra.x = (p0+ac   < PP) ? rp[p0+ac]   : 0.f; \
            ra.y = (p0+ac+1 < PP) ? rp[p0+ac+1] : 0.f; \
            ra.z = (p0+ac+2 < PP) ? rp[p0+ac+2] : 0.f; \
            ra.w = (p0+ac+3 < PP) ? rp[p0+ac+3] : 0.f; \
        } \
        _Pragma("unroll") \
        for (int s = 0; s < 4; s++) \
            rw[s] = *(const float4*)&w2[(wo + s * 64) * 128 + (qc) + wq]; \
    } while (0)
    #define GELU4(v, row) do { \
        float sc_ = sScale[row], sh_ = sShift[row]; \
        v.x = v.x * sc_ + sh_; v.x = 0.5f * v.x * (1.f + erff(v.x * 0.70710678118654752f)); \
        v.y = v.y * sc_ + sh_; v.y = 0.5f * v.y * (1.f + erff(v.y * 0.70710678118654752f)); \
        v.z = v.z * sc_ + sh_; v.z = 0.5f * v.z * (1.f + erff(v.z * 0.70710678118654752f)); \
        v.w = v.w * sc_ + sh_; v.w = 0.5f * v.w * (1.f + erff(v.w * 0.70710678118654752f)); \
    } while (0)
    #define G2_STORE(st, qc) do { \
        GELU4(ra, (qc) + ar); \
        *(uint4*)&sA[st][ar][ac] = tf4(ra); \
        _Pragma("unroll") \
        for (int s = 0; s < 4; s++) { \
            sWt[st][wq + 0][wo + s * 64] = f2tf32(rw[s].x); \
            sWt[st][wq + 1][wo + s * 64] = f2tf32(rw[s].y); \
            sWt[st][wq + 2][wo + s * 64] = f2tf32(rw[s].z); \
            sWt[st][wq + 3][wo + s * 64] = f2tf32(rw[s].w); \
        } \
    } while (0)

    G2_LOAD(0); G2_STORE(0, 0);
    __syncthreads();
    int cur = 0;
    for (int qc = 0; qc < 128; qc += 16) {
        const bool hasnext = (qc + 16 < 128);
        if (hasnext) G2_LOAD(qc + 16);
        #pragma unroll
        for (int ks = 0; ks < 2; ks++) {
            int k0 = ks * 8;
            uint32_t afr[4][4];
            #pragma unroll
            for (int mt = 0; mt < 4; mt++) {
                int o = obase + mt * 16 + gid;
                afr[mt][0] = sWt[cur][k0 + tig][o];
                afr[mt][1] = sWt[cur][k0 + tig][o + 8];
                afr[mt][2] = sWt[cur][k0 + tig + 4][o];
                afr[mt][3] = sWt[cur][k0 + tig + 4][o + 8];
            }
            #pragma unroll
            for (int nt = 0; nt < 4; nt++) {
                uint32_t bfr[2];
                int p = pbase + nt * 8 + gid;
                bfr[0] = sA[cur][k0 + tig][p];
                bfr[1] = sA[cur][k0 + tig + 4][p];
                #pragma unroll
                for (int mt = 0; mt < 4; mt++)
                    mma_tf32(acc[mt][nt], afr[mt], bfr);
            }
        }
        if (hasnext) G2_STORE(cur ^ 1, qc + 16);
        __syncthreads();
        cur ^= 1;
    }
    float* gbuf = g_ff + (size_t)b * 256 * PSTR;
    #pragma unroll
    for (int mt = 0; mt < 4; mt++) {
        int o1 = obase + mt * 16 + gid;
        float ga = g_gates[b * 4 + (o1 >> 6)];
        float gb_ = g_gates[b * 4 + ((o1 + 8) >> 6)];
        float bia = b2[o1], bib = b2[o1 + 8];
        #pragma unroll
        for (int nt = 0; nt < 4; nt++) {
            int p = p0 + pbase + nt * 8 + 2 * tig;
            float vx = (acc[mt][nt].x + bia) * ga, vy = (acc[mt][nt].y + bia) * ga;
            float vz = (acc[mt][nt].z + bib) * gb_, vw = (acc[mt][nt].w + bib) * gb_;
            if (fullA) {
                *(float2*)&gbuf[(size_t)o1 * PSTR + p] = make_float2(vx, vy);
                *(float2*)&gbuf[(size_t)(o1 + 8) * PSTR + p] = make_float2(vz, vw);
            } else {
                if (p < PP)     { gbuf[(size_t)o1*PSTR + p] = vx;     gbuf[(size_t)(o1+8)*PSTR + p] = vz; }
                if (p + 1 < PP) { gbuf[(size_t)o1*PSTR + p + 1] = vy; gbuf[(size_t)(o1+8)*PSTR + p + 1] = vw; }
            }
        }
    }
}

// ---------------- K6: IDWT2 -> g_recon (R5 tiling) ----------------
__global__ void __launch_bounds__(256) k_idwt() {
    int tile = blockIdx.x;         // 0..31 : 8 h-tiles x 4 w-tiles
    int bc = blockIdx.y;
    int h0 = (tile >> 2) * 32;
    int w0 = (tile & 3) * 64;
    int b = bc >> 6, c = bc & 63;
    __shared__ float scoef[4][19][36];
    __shared__ float stmp[4][19][68];
    const float* gb = g_ff + ((size_t)b * 256 + c) * PSTR;
    int ib0 = h0 >> 1, jb0 = w0 >> 1;

    for (int idx = threadIdx.x; idx < 4 * 19 * 35; idx += 256) {
        int k = idx / (19 * 35); int rem = idx % (19 * 35);
        int il = rem / 35, jl = rem % 35;
        scoef[k][il][jl] = gb[(size_t)k * 64 * PSTR + (ib0 + il) * OWW + jb0 + jl];
    }
    __syncthreads();
    for (int s = threadIdx.x; s < 19 * 16; s += 256) {
        int il = s >> 4, ws = s & 15;
        int wl = ws * 4, jb = wl >> 1;
        #pragma unroll
        for (int k = 0; k < 4; k++) {
            const float* fc = (k < 2) ? DEC_LO : DEC_HI;
            float c0 = scoef[k][il][jb],     c1 = scoef[k][il][jb + 1];
            float c2 = scoef[k][il][jb + 2], c3 = scoef[k][il][jb + 3];
            float c4 = scoef[k][il][jb + 4];
            stmp[k][il][wl + 0] = c0*fc[1] + c1*fc[3] + c2*fc[5] + c3*fc[7];
            stmp[k][il][wl + 1] = c0*fc[0] + c1*fc[2] + c2*fc[4] + c3*fc[6];
            stmp[k][il][wl + 2] = c1*fc[1] + c2*fc[3] + c3*fc[5] + c4*fc[7];
            stmp[k][il][wl + 3] = c1*fc[0] + c2*fc[2] + c3*fc[4] + c4*fc[6];
        }
    }
    __syncthreads();
    float* rb = g_recon + ((size_t)b * 64 + c) * HWSZ;
    for (int s = threadIdx.x; s < 512; s += 256) {
        int wlh = s & 63, hs = s >> 6;
        int hb = hs * 4, ib = hb >> 1;
        float t[4][5];
        #pragma unroll
        for (int k = 0; k < 4; k++)
            #pragma unroll
            for (int m = 0; m < 5; m++)
                t[k][m] = stmp[k][ib + m][wlh];
        #pragma unroll
        for (int dh = 0; dh < 4; dh++) {
            int sh = dh >> 1;
            float acc = 0.f;
            #pragma unroll
            for (int k = 0; k < 4; k++) {
                const float* fr = (k & 1) ? DEC_HI : DEC_LO;
                if (dh & 1)
                    acc += t[k][sh]*fr[0] + t[k][sh+1]*fr[2] + t[k][sh+2]*fr[4] + t[k][sh+3]*fr[6];
                else
                    acc += t[k][sh]*fr[1] + t[k][sh+1]*fr[3] + t[k][sh+2]*fr[5] + t[k][sh+3]*fr[7];
            }
            rb[(h0 + hb + dh) * WW + w0 + wlh] = acc;
        }
    }
}

// ---------------- K7: fused = [x, recon] @ wf^T + bf (tf32, pipelined) ----------------
__global__ void __launch_bounds__(256) k_final(const float* __restrict__ x,
                                               const float* __restrict__ wf,
                                               const float* __restrict__ bf,
                                               float* __restrict__ out) {
    const int b = blockIdx.y;
    const int p0 = blockIdx.x * 256;
    __shared__ uint32_t sW[2][64][20];
    __shared__ uint32_t sA[2][16][264];
    const int tid = threadIdx.x;
    const int w = tid >> 5, lane = tid & 31;
    const int gid = lane >> 2, tig = lane & 3;
    const int obase = (w >> 2) * 32, pbase = (w & 3) * 64;
    float4 acc[2][8] = {};
    const float* xb = x + (size_t)b * 64 * HWSZ;
    const float* rb = g_recon + (size_t)b * 64 * HWSZ;

    const int ar0 = tid >> 6;
    const int ac0 = (tid & 63) * 4;
    const int wo0 = tid >> 2, wq0 = (tid & 3) * 4;
    float4 ra[4], rw0;

    #define G3_LOAD(cc) do { \
        _Pragma("unroll") \
        for (int s = 0; s < 4; s++) { \
            int ch = (cc) + ar0 + s * 4; \
            const float* src = (ch < 64) ? &xb[(size_t)ch * HWSZ] : &rb[(size_t)(ch - 64) * HWSZ]; \
            ra[s] = *(const float4*)&src[p0 + ac0]; \
        } \
        rw0 = *(const float4*)&wf[wo0 * 128 + (cc) + wq0]; \
    } while (0)
    #define G3_STORE(st) do { \
        _Pragma("unroll") \
        for (int s = 0; s < 4; s++) \
            *(uint4*)&sA[st][ar0 + s * 4][ac0] = tf4(ra[s]); \
        *(uint4*)&sW[st][wo0][wq0] = tf4(rw0); \
    } while (0)

    G3_LOAD(0); G3_STORE(0);
    __syncthreads();
    int cur = 0;
    for (int cc = 0; cc < 128; cc += 16) {
        const bool hasnext = (cc + 16 < 128);
        if (hasnext) G3_LOAD(cc + 16);
        #pragma unroll
        for (int ks = 0; ks < 2; ks++) {
            int k0 = ks * 8;
            uint32_t afr[2][4];
            #pragma unroll
            for (int mt = 0; mt < 2; mt++) {
                int o = obase + mt * 16 + gid;
                afr[mt][0] = sW[cur][o][k0 + tig];
                afr[mt][1] = sW[cur][o + 8][k0 + tig];
                afr[mt][2] = sW[cur][o][k0 + tig + 4];
                afr[mt][3] = sW[cur][o + 8][k0 + tig + 4];
            }
            #pragma unroll
            for (int nt = 0; nt < 8; nt++) {
                uint32_t bfr[2];
                int p = pbase + nt * 8 + gid;
                bfr[0] = sA[cur][k0 + tig][p];
                bfr[1] = sA[cur][k0 + tig + 4][p];
                mma_tf32(acc[0][nt], afr[0], bfr);
                mma_tf32(acc[1][nt], afr[1], bfr);
            }
        }
        if (hasnext) G3_STORE(cur ^ 1);
        __syncthreads();
        cur ^= 1;
    }
    float* ob = out + (size_t)b * 64 * HWSZ;
    #pragma unroll
    for (int mt = 0; mt < 2; mt++) {
        int o1 = obase + mt * 16 + gid;
        float bia = bf[o1], bib = bf[o1 + 8];
        #pragma unroll
        for (int nt = 0; nt < 8; nt++) {
            int p = p0 + pbase + nt * 8 + 2 * tig;
            *(float2*)&ob[(size_t)o1 * HWSZ + p] = make_float2(acc[mt][nt].x + bia, acc[mt][nt].y + bia);
            *(float2*)&ob[(size_t)(o1 + 8) * HWSZ + p] = make_float2(acc[mt][nt].z + bib, acc[mt][nt].w + bib);
        }
    }
}

extern "C" void kernel_launch(void* const* d_in, const int* in_sizes, int n_in,
                              void* d_out, int out_size) {
    const float* x     = (const float*)d_in[0];
    const float* w1    = (const float*)d_in[1];
    const float* b1    = (const float*)d_in[2];
    const float* gamma = (const float*)d_in[3];
    const float* beta  = (const float*)d_in[4];
    const float* w2    = (const float*)d_in[5];
    const float* b2    = (const float*)d_in[6];
    const float* g1    = (const float*)d_in[7];
    const float* gb1   = (const float*)d_in[8];
    const float* g2    = (const float*)d_in[9];
    const float* gb2   = (const float*)d_in[10];
    const float* wf    = (const float*)d_in[11];
    const float* bf    = (const float*)d_in[12];
    float* out = (float*)d_out;

    // launch order chosen so k_gemm1 sits at profiled launch index 3
    k_density<<<256, 256>>>(x, 0);
    k_density<<<256, 256>>>(x, 256);
    k_dwt<<<dim3(17, 512), 256>>>(x);
    k_gemm1<<<dim3(135, 8), 256>>>(w1, b1);
    k_small<<<1, 256>>>(g1, gb1, g2, gb2);
    k_gemm2<<<dim3(269, 8), 256>>>(w2, b2, gamma, beta);
    k_idwt<<<dim3(32, 512), 256>>>();
    k_final<<<dim3(256, 8), 256>>>(x, wf, bf, out);
}

// round 8
// speedup vs baseline: 1.1719x; 1.0819x over previous
#include <cuda_runtime.h>
#include <stdint.h>
#include <math.h>

#define BB 8
#define CC 64
#define HH 256
#define WW 256
#define OHH 131
#define OWW 131
#define PP (OHH*OWW)      /* 17161 */
#define PSTR 17164        /* padded channel stride (multiple of 4) */
#define HWSZ (HH*WW)      /* 65536 */

// db4 filters
__constant__ float DEC_LO[8] = {
    -0.010597401784997278f, 0.032883011666982945f, 0.030841381835986965f,
    -0.18703481171888114f, -0.02798376941698385f, 0.6308807679295904f,
    0.7148465705525415f, 0.23037781330885523f };
__constant__ float DEC_HI[8] = {
    -0.23037781330885523f, 0.7148465705525415f, -0.6308807679295904f,
    -0.02798376941698385f, 0.18703481171888114f, 0.030841381835986965f,
    -0.032883011666982945f, -0.010597401784997278f };

// Scratch (device globals; allocation-free rule). +4096 slack for cp.async tail reads.
__device__ __align__(16) float g_ff[(size_t)BB*256*PSTR + 4096];
__device__ __align__(16) float g_z[(size_t)BB*128*PSTR + 4096];
__device__ __align__(16) float g_recon[(size_t)BB*64*HWSZ];
__device__ __align__(16) float g_w1r[128*256];   // tf32-rounded weights
__device__ __align__(16) float g_w2r[256*128];
__device__ __align__(16) float g_wfr[64*128];
__device__ float g_stats[128];                 // (b,g): sum, sumsq
__device__ float g_density[512];               // raw nonzero counts
__device__ float g_munorm[128];                // (b,g): mu, rsig
__device__ float g_gates[32];                  // (b, k)

// ---- tf32 helpers ----
__device__ __forceinline__ uint32_t f2tf32(float x) {
    uint32_t r; asm("cvt.rna.tf32.f32 %0, %1;" : "=r"(r) : "f"(x)); return r;
}
__device__ __forceinline__ float rtf(float x) { return __uint_as_float(f2tf32(x)); }
__device__ __forceinline__ void mma_tf32(float4& d, const uint32_t a[4], const uint32_t b[2]) {
    asm volatile("mma.sync.aligned.m16n8k8.row.col.f32.tf32.tf32.f32 "
        "{%0,%1,%2,%3}, {%4,%5,%6,%7}, {%8,%9}, {%0,%1,%2,%3};"
        : "+f"(d.x), "+f"(d.y), "+f"(d.z), "+f"(d.w)
        : "r"(a[0]), "r"(a[1]), "r"(a[2]), "r"(a[3]), "r"(b[0]), "r"(b[1]));
}
__device__ __forceinline__ uint4 tf4(float4 v) {
    uint4 u; u.x = f2tf32(v.x); u.y = f2tf32(v.y); u.z = f2tf32(v.z); u.w = f2tf32(v.w);
    return u;
}

// ---------------- K0: prep — round weights to tf32, zero accumulators ----------------
__global__ void k_prep(const float* __restrict__ w1, const float* __restrict__ w2,
                       const float* __restrict__ wf, int phase) {
    int i = blockIdx.x * 256 + threadIdx.x;     // grid 128 -> 32768
    if (phase == 0) {
        g_w1r[i] = rtf(w1[i]);
        if (i < 512) g_density[i] = 0.f;
        if (i < 128) g_stats[i] = 0.f;
    } else {
        g_w2r[i] = rtf(w2[i]);
        if (i < 8192) g_wfr[i] = rtf(wf[i]);
    }
}

// ---------------- K2: DWT2 -> g_ff (tf32-rounded) + inline density count ----------------
__global__ void __launch_bounds__(256) k_dwt(const float* __restrict__ x) {
    const int gi0 = blockIdx.x * 8;
    const int bc = blockIdx.y;
    __shared__ float sIn[22][272];
    __shared__ float sT[2][22][132];
    const float* xp = x + (size_t)bc * HWSZ;

    // bulk rows; bands 0..15 uniquely own orig rows 2gi0..2gi0+15 == sIn rows 6..21
    int cnt = 0;
    const bool owner = (blockIdx.x < 16);
    for (int idx = threadIdx.x; idx < 22 * 64; idx += 256) {
        int r = idx >> 6, q = idx & 63;
        int m = 2 * gi0 - 6 + r;
        m = (m < 0) ? (-1 - m) : ((m > 255) ? (511 - m) : m);
        float4 v = *(const float4*)&xp[m * 256 + 4 * q];
        *(float4*)&sIn[r][8 + 4 * q] = v;
        if (owner && r >= 6)
            cnt += (v.x != 0.f) + (v.y != 0.f) + (v.z != 0.f) + (v.w != 0.f);
    }
    if (owner) {
        #pragma unroll
        for (int off = 16; off > 0; off >>= 1)
            cnt += __shfl_down_sync(0xffffffffu, cnt, off);
        if ((threadIdx.x & 31) == 0 && cnt > 0)
            atomicAdd(&g_density[bc], (float)cnt);
    }
    for (int idx = threadIdx.x; idx < 22 * 12; idx += 256) {
        int r = idx / 12, e = idx % 12;
        int m = 2 * gi0 - 6 + r;
        m = (m < 0) ? (-1 - m) : ((m > 255) ? (511 - m) : m);
        int col = (e < 6) ? (2 + e) : (258 + e);
        int n = (e < 6) ? (5 - e) : (261 - e);
        sIn[r][col] = xp[m * 256 + n];
    }
    __syncthreads();
    for (int idx = threadIdx.x; idx < 22 * 131; idx += 256) {
        int r = idx / 131, j = idx % 131;
        float lo = 0.f, hi = 0.f;
        #pragma unroll
        for (int v = 0; v < 8; v++) {
            float xv = sIn[r][2 * j + v + 2];
            lo += xv * DEC_LO[7 - v];
            hi += xv * DEC_HI[7 - v];
        }
        sT[0][r][j] = lo; sT[1][r][j] = hi;
    }
    __syncthreads();
    int b = bc >> 6, c = bc & 63;
    float* base = g_ff + ((size_t)b * 256 + c) * PSTR;
    for (int idx = threadIdx.x; idx < 8 * 131; idx += 256) {
        int ii = idx / 131, j = idx % 131;
        int gi = gi0 + ii;
        if (gi < OHH) {
            float aa = 0.f, da = 0.f, ad = 0.f, dd = 0.f;
            #pragma unroll
            for (int u = 0; u < 8; u++) {
                float tl = sT[0][2 * ii + u][j], th = sT[1][2 * ii + u][j];
                float gl = DEC_LO[7 - u], gh = DEC_HI[7 - u];
                aa += gl * tl; da += gh * tl; ad += gl * th; dd += gh * th;
            }
            int p = gi * OWW + j;
            base[p] = rtf(aa);
            base[(size_t)64 * PSTR + p] = rtf(da);
            base[(size_t)128 * PSTR + p] = rtf(ad);
            base[(size_t)192 * PSTR + p] = rtf(dd);
        }
    }
}

// ---------------- K3: z = ff @ w1^T + b1, + GN stats (cp.async 4-stage) ----------------
#define G1_STAGES 4
#define G1_SA 2176   /* 16*136 uint32 */
#define G1_SW 2560   /* 128*20 uint32 */
#define G1_SMEM (G1_STAGES*(G1_SA+G1_SW)*4)

__global__ void __launch_bounds__(256) k_gemm1(const float* __restrict__ b1) {
    extern __shared__ uint32_t smem[];
    uint32_t* sAb = smem;                       // [stage][16][136]
    uint32_t* sWb = smem + G1_STAGES * G1_SA;   // [stage][128][20]
    const int b = blockIdx.y;
    const int p0 = blockIdx.x * 128;
    const int tid = threadIdx.x;
    const float* ffb = g_ff + (size_t)b * 256 * PSTR;
    uint32_t saddrA = (uint32_t)__cvta_generic_to_shared(sAb);
    uint32_t saddrW = (uint32_t)__cvta_generic_to_shared(sWb);

    #define G1_ISSUE(stage, qc) do { \
        _Pragma("unroll") \
        for (int h = 0; h < 2; h++) { \
            int cch = tid + h * 256; \
            int r_ = cch >> 5, col_ = (cch & 31) * 4; \
            const float* src = ffb + (size_t)((qc) + r_) * PSTR + p0 + col_; \
            uint32_t dst = saddrA + (uint32_t)(((stage) * G1_SA + r_ * 136 + col_) * 4); \
            int rem = PP - (p0 + col_); \
            int bytes = (rem >= 4) ? 16 : ((rem > 0) ? rem * 4 : 0); \
            asm volatile("cp.async.ca.shared.global [%0], [%1], 16, %2;" \
                         :: "r"(dst), "l"(src), "r"(bytes)); \
        } \
        _Pragma("unroll") \
        for (int h = 0; h < 2; h++) { \
            int cch = tid + h * 256; \
            int o_ = cch >> 2, k4_ = (cch & 3) * 4; \
            const float* src = g_w1r + o_ * 256 + (qc) + k4_; \
            uint32_t dst = saddrW + (uint32_t)(((stage) * G1_SW + o_ * 20 + k4_) * 4); \
            asm volatile("cp.async.ca.shared.global [%0], [%1], 16;" \
                         :: "r"(dst), "l"(src)); \
        } \
    } while (0)

    G1_ISSUE(0, 0);   asm volatile("cp.async.commit_group;" ::: "memory");
    G1_ISSUE(1, 16);  asm volatile("cp.async.commit_group;" ::: "memory");
    G1_ISSUE(2, 32);  asm volatile("cp.async.commit_group;" ::: "memory");

    const int w = tid >> 5, lane = tid & 31;
    const int gid = lane >> 2, tig = lane & 3;
    const int obase = (w >> 1) * 32, pbase = (w & 1) * 64;
    float4 acc[2][8] = {};
    const bool fullA = (p0 + 128 <= PP);

    for (int i = 0; i < 16; i++) {
        asm volatile("cp.async.wait_group 2;" ::: "memory");
        __syncthreads();
        if (i + 3 < 16) { G1_ISSUE((i + 3) & 3, (i + 3) * 16); }
        asm volatile("cp.async.commit_group;" ::: "memory");
        const uint32_t* cA = sAb + (i & 3) * G1_SA;
        const uint32_t* cW = sWb + (i & 3) * G1_SW;
        #pragma unroll
        for (int ks = 0; ks < 2; ks++) {
            int k0 = ks * 8;
            uint32_t afr[2][4];
            #pragma unroll
            for (int mt = 0; mt < 2; mt++) {
                int o = obase + mt * 16 + gid;
                afr[mt][0] = cW[o * 20 + k0 + tig];
                afr[mt][1] = cW[(o + 8) * 20 + k0 + tig];
                afr[mt][2] = cW[o * 20 + k0 + tig + 4];
                afr[mt][3] = cW[(o + 8) * 20 + k0 + tig + 4];
            }
            #pragma unroll
            for (int nt = 0; nt < 8; nt++) {
                uint32_t bfr[2];
                int p = pbase + nt * 8 + gid;
                bfr[0] = cA[(k0 + tig) * 136 + p];
                bfr[1] = cA[(k0 + tig + 4) * 136 + p];
                mma_tf32(acc[0][nt], afr[0], bfr);
                mma_tf32(acc[1][nt], afr[1], bfr);
            }
        }
    }
    // epilogue: +bias, store z, GN stats
    float s1[2] = {0.f, 0.f}, s2[2] = {0.f, 0.f};
    float* zb = g_z + (size_t)b * 128 * PSTR;
    #pragma unroll
    for (int mt = 0; mt < 2; mt++) {
        int o1 = obase + mt * 16 + gid;
        float bia = b1[o1], bib = b1[o1 + 8];
        #pragma unroll
        for (int nt = 0; nt < 8; nt++) {
            int p = p0 + pbase + nt * 8 + 2 * tig;
            float vx = acc[mt][nt].x + bia, vy = acc[mt][nt].y + bia;
            float vz = acc[mt][nt].z + bib, vw = acc[mt][nt].w + bib;
            if (fullA) {
                s1[mt] += vx + vy + vz + vw;
                s2[mt] += vx*vx + vy*vy + vz*vz + vw*vw;
                *(float2*)&zb[(size_t)o1 * PSTR + p] = make_float2(vx, vy);
                *(float2*)&zb[(size_t)(o1 + 8) * PSTR + p] = make_float2(vz, vw);
            } else {
                if (p < PP)     { zb[(size_t)o1*PSTR + p] = vx;       zb[(size_t)(o1+8)*PSTR + p] = vz;       s1[mt] += vx + vz; s2[mt] += vx*vx + vz*vz; }
                if (p + 1 < PP) { zb[(size_t)o1*PSTR + p + 1] = vy;   zb[(size_t)(o1+8)*PSTR + p + 1] = vw;   s1[mt] += vy + vw; s2[mt] += vy*vy + vw*vw; }
            }
        }
    }
    #pragma unroll
    for (int off = 16; off > 0; off >>= 1) {
        s1[0] += __shfl_down_sync(0xffffffffu, s1[0], off);
        s2[0] += __shfl_down_sync(0xffffffffu, s2[0], off);
        s1[1] += __shfl_down_sync(0xffffffffu, s1[1], off);
        s2[1] += __shfl_down_sync(0xffffffffu, s2[1], off);
    }
    if (lane == 0) {
        int g0 = (w >> 1) * 2;
        atomicAdd(&g_stats[(b * 8 + g0) * 2],     s1[0]);
        atomicAdd(&g_stats[(b * 8 + g0) * 2 + 1], s2[0]);
        atomicAdd(&g_stats[(b * 8 + g0 + 1) * 2],     s1[1]);
        atomicAdd(&g_stats[(b * 8 + g0 + 1) * 2 + 1], s2[1]);
    }
}

// ---------------- K4: finalize stats + gates (warp-parallel) ----------------
__global__ void k_small(const float* __restrict__ g1, const float* __restrict__ gb1,
                        const float* __restrict__ g2, const float* __restrict__ gb2) {
    int t = threadIdx.x;
    if (t < 64) {
        float s1 = g_stats[2 * t], s2 = g_stats[2 * t + 1];
        float invN = 1.f / (16.f * (float)PP);
        float mu = s1 * invN;
        float var = s2 * invN - mu * mu;
        g_munorm[2 * t] = mu;
        g_munorm[2 * t + 1] = rsqrtf(var + 1e-5f);
    }
    __shared__ float sh[8][16];
    int w = t >> 5, lane = t & 31;
    const float invHW = 1.f / (float)HWSZ;
    if (lane < 16) {
        float s = gb1[lane];
        #pragma unroll 4
        for (int c = 0; c < 64; c++) s += (g_density[w * 64 + c] * invHW) * g1[lane * 64 + c];
        sh[w][lane] = fmaxf(s, 0.f);
    }
    __syncwarp();
    if (lane < 4) {
        float s = gb2[lane];
        #pragma unroll
        for (int i = 0; i < 16; i++) s += sh[w][i] * g2[lane * 16 + i];
        g_gates[w * 4 + lane] = 1.f / (1.f + expf(-s));
    }
}

// ---------------- K5: gated = (gelu(GN(z)) @ w2^T + b2) * gate ----------------
__global__ void __launch_bounds__(256) k_gemm2(const float* __restrict__ b2,
                                               const float* __restrict__ gamma,
                                               const float* __restrict__ beta) {
    const int b = blockIdx.y;
    const int p0 = blockIdx.x * 64;
    __shared__ uint32_t sWt[2][16][260];   // K-major W tile
    __shared__ uint32_t sA[2][16][72];
    __shared__ float sScale[128], sShift[128];
    const int tid = threadIdx.x;
    if (tid < 128) {
        int q = tid, g = q >> 4;
        float mu = g_munorm[(b * 8 + g) * 2];
        float rs = g_munorm[(b * 8 + g) * 2 + 1];
        float sc = rs * gamma[q];
        sScale[q] = sc;
        sShift[q] = beta[q] - mu * sc;
    }
    __syncthreads();
    const int w = tid >> 5, lane = tid & 31;
    const int gid = lane >> 2, tig = lane & 3;
    const int obase = (w >> 1) * 64, pbase = (w & 1) * 32;
    float4 acc[4][4] = {};
    const float* zb = g_z + (size_t)b * 128 * PSTR;
    const bool fullA = (p0 + 64 <= PP);

    const int ar = tid >> 4, ac = (tid & 15) * 4;
    const int wo = tid >> 2, wq = (tid & 3) * 4;
    float4 ra, rw[4];

    #define G2_LOAD(qc) do { \
        if (fullA) { \
            ra = *(const float4*)&zb[(size_t)((qc) + ar) * PSTR + p0 + ac]; \
        } else { \
            const float* rp = &zb[(size_t)((qc) + ar) * PSTR]; \
            ra.x = (p0+ac   < PP) ? rp[p0+ac]   : 0.f; \
            ra.y = (p0+ac+1 < PP) ? rp[p0+ac+1] : 0.f; \
            ra.z = (p0+ac+2 < PP) ? rp[p0+ac+2] : 0.f; \
            ra.w = (p0+ac+3 < PP) ? rp[p0+ac+3] : 0.f; \
        } \
        _Pragma("unroll") \
        for (int s = 0; s < 4; s++) \
            rw[s] = *(const float4*)&g_w2r[(wo + s * 64) * 128 + (qc) + wq]; \
    } while (0)
    #define GELU4(v, row) do { \
        float sc_ = sScale[row], sh_ = sShift[row]; \
        v.x = v.x * sc_ + sh_; v.x = 0.5f * v.x * (1.f + erff(v.x * 0.70710678118654752f)); \
        v.y = v.y * sc_ + sh_; v.y = 0.5f * v.y * (1.f + erff(v.y * 0.70710678118654752f)); \
        v.z = v.z * sc_ + sh_; v.z = 0.5f * v.z * (1.f + erff(v.z * 0.70710678118654752f)); \
        v.w = v.w * sc_ + sh_; v.w = 0.5f * v.w * (1.f + erff(v.w * 0.70710678118654752f)); \
    } while (0)
    #define G2_STORE(st, qc) do { \
        GELU4(ra, (qc) + ar); \
        *(uint4*)&sA[st][ar][ac] = tf4(ra); \
        _Pragma("unroll") \
        for (int s = 0; s < 4; s++) { \
            sWt[st][wq + 0][wo + s * 64] = __float_as_uint(rw[s].x); \
            sWt[st][wq + 1][wo + s * 64] = __float_as_uint(rw[s].y); \
            sWt[st][wq + 2][wo + s * 64] = __float_as_uint(rw[s].z); \
            sWt[st][wq + 3][wo + s * 64] = __float_as_uint(rw[s].w); \
        } \
    } while (0)

    G2_LOAD(0); G2_STORE(0, 0);
    __syncthreads();
    int cur = 0;
    for (int qc = 0; qc < 128; qc += 16) {
        const bool hasnext = (qc + 16 < 128);
        if (hasnext) G2_LOAD(qc + 16);
        #pragma unroll
        for (int ks = 0; ks < 2; ks++) {
            int k0 = ks * 8;
            uint32_t afr[4][4];
            #pragma unroll
            for (int mt = 0; mt < 4; mt++) {
                int o = obase + mt * 16 + gid;
                afr[mt][0] = sWt[cur][k0 + tig][o];
                afr[mt][1] = sWt[cur][k0 + tig][o + 8];
                afr[mt][2] = sWt[cur][k0 + tig + 4][o];
                afr[mt][3] = sWt[cur][k0 + tig + 4][o + 8];
            }
            #pragma unroll
            for (int nt = 0; nt < 4; nt++) {
                uint32_t bfr[2];
                int p = pbase + nt * 8 + gid;
                bfr[0] = sA[cur][k0 + tig][p];
                bfr[1] = sA[cur][k0 + tig + 4][p];
                #pragma unroll
                for (int mt = 0; mt < 4; mt++)
                    mma_tf32(acc[mt][nt], afr[mt], bfr);
            }
        }
        if (hasnext) G2_STORE(cur ^ 1, qc + 16);
        __syncthreads();
        cur ^= 1;
    }
    float* gbuf = g_ff + (size_t)b * 256 * PSTR;
    #pragma unroll
    for (int mt = 0; mt < 4; mt++) {
        int o1 = obase + mt * 16 + gid;
        float ga = g_gates[b * 4 + (o1 >> 6)];
        float gb_ = g_gates[b * 4 + ((o1 + 8) >> 6)];
        float bia = b2[o1], bib = b2[o1 + 8];
        #pragma unroll
        for (int nt = 0; nt < 4; nt++) {
            int p = p0 + pbase + nt * 8 + 2 * tig;
            float vx = (acc[mt][nt].x + bia) * ga, vy = (acc[mt][nt].y + bia) * ga;
            float vz = (acc[mt][nt].z + bib) * gb_, vw = (acc[mt][nt].w + bib) * gb_;
            if (fullA) {
                *(float2*)&gbuf[(size_t)o1 * PSTR + p] = make_float2(vx, vy);
                *(float2*)&gbuf[(size_t)(o1 + 8) * PSTR + p] = make_float2(vz, vw);
            } else {
                if (p < PP)     { gbuf[(size_t)o1*PSTR + p] = vx;     gbuf[(size_t)(o1+8)*PSTR + p] = vz; }
                if (p + 1 < PP) { gbuf[(size_t)o1*PSTR + p + 1] = vy; gbuf[(size_t)(o1+8)*PSTR + p + 1] = vw; }
            }
        }
    }
}

// ---------------- K6: IDWT2 -> g_recon (R5 tiling) ----------------
__global__ void __launch_bounds__(256) k_idwt() {
    int tile = blockIdx.x;         // 0..31 : 8 h-tiles x 4 w-tiles
    int bc = blockIdx.y;
    int h0 = (tile >> 2) * 32;
    int w0 = (tile & 3) * 64;
    int b = bc >> 6, c = bc & 63;
    __shared__ float scoef[4][19][36];
    __shared__ float stmp[4][19][68];
    const float* gb = g_ff + ((size_t)b * 256 + c) * PSTR;
    int ib0 = h0 >> 1, jb0 = w0 >> 1;

    for (int idx = threadIdx.x; idx < 4 * 19 * 35; idx += 256) {
        int k = idx / (19 * 35); int rem = idx % (19 * 35);
        int il = rem / 35, jl = rem % 35;
        scoef[k][il][jl] = gb[(size_t)k * 64 * PSTR + (ib0 + il) * OWW + jb0 + jl];
    }
    __syncthreads();
    for (int s = threadIdx.x; s < 19 * 16; s += 256) {
        int il = s >> 4, ws = s & 15;
        int wl = ws * 4, jb = wl >> 1;
        #pragma unroll
        for (int k = 0; k < 4; k++) {
            const float* fc = (k < 2) ? DEC_LO : DEC_HI;
            float c0 = scoef[k][il][jb],     c1 = scoef[k][il][jb + 1];
            float c2 = scoef[k][il][jb + 2], c3 = scoef[k][il][jb + 3];
            float c4 = scoef[k][il][jb + 4];
            stmp[k][il][wl + 0] = c0*fc[1] + c1*fc[3] + c2*fc[5] + c3*fc[7];
            stmp[k][il][wl + 1] = c0*fc[0] + c1*fc[2] + c2*fc[4] + c3*fc[6];
            stmp[k][il][wl + 2] = c1*fc[1] + c2*fc[3] + c3*fc[5] + c4*fc[7];
            stmp[k][il][wl + 3] = c1*fc[0] + c2*fc[2] + c3*fc[4] + c4*fc[6];
        }
    }
    __syncthreads();
    float* rb = g_recon + ((size_t)b * 64 + c) * HWSZ;
    for (int s = threadIdx.x; s < 512; s += 256) {
        int wlh = s & 63, hs = s >> 6;
        int hb = hs * 4, ib = hb >> 1;
        float t[4][5];
        #pragma unroll
        for (int k = 0; k < 4; k++)
            #pragma unroll
            for (int m = 0; m < 5; m++)
                t[k][m] = stmp[k][ib + m][wlh];
        #pragma unroll
        for (int dh = 0; dh < 4; dh++) {
            int sh = dh >> 1;
            float acc = 0.f;
            #pragma unroll
            for (int k = 0; k < 4; k++) {
                const float* fr = (k & 1) ? DEC_HI : DEC_LO;
                if (dh & 1)
                    acc += t[k][sh]*fr[0] + t[k][sh+1]*fr[2] + t[k][sh+2]*fr[4] + t[k][sh+3]*fr[6];
                else
                    acc += t[k][sh]*fr[1] + t[k][sh+1]*fr[3] + t[k][sh+2]*fr[5] + t[k][sh+3]*fr[7];
            }
            rb[(h0 + hb + dh) * WW + w0 + wlh] = acc;
        }
    }
}

// ---------------- K7: fused = [x, recon] @ wf^T + bf (tf32, pipelined) ----------------
__global__ void __launch_bounds__(256) k_final(const float* __restrict__ x,
                                               const float* __restrict__ bf,
                                               float* __restrict__ out) {
    const int b = blockIdx.y;
    const int p0 = blockIdx.x * 256;
    __shared__ uint32_t sW[2][64][20];
    __shared__ uint32_t sA[2][16][264];
    const int tid = threadIdx.x;
    const int w = tid >> 5, lane = tid & 31;
    const int gid = lane >> 2, tig = lane & 3;
    const int obase = (w >> 2) * 32, pbase = (w & 3) * 64;
    float4 acc[2][8] = {};
    const float* xb = x + (size_t)b * 64 * HWSZ;
    const float* rb = g_recon + (size_t)b * 64 * HWSZ;

    const int ar0 = tid >> 6;
    const int ac0 = (tid & 63) * 4;
    const int wo0 = tid >> 2, wq0 = (tid & 3) * 4;
    float4 ra[4], rw0;

    #define G3_LOAD(cc) do { \
        _Pragma("unroll") \
        for (int s = 0; s < 4; s++) { \
            int ch = (cc) + ar0 + s * 4; \
            const float* src = (ch < 64) ? &xb[(size_t)ch * HWSZ] : &rb[(size_t)(ch - 64) * HWSZ]; \
            ra[s] = *(const float4*)&src[p0 + ac0]; \
        } \
        rw0 = *(const float4*)&g_wfr[wo0 * 128 + (cc) + wq0]; \
    } while (0)
    #define G3_STORE(st) do { \
        _Pragma("unroll") \
        for (int s = 0; s < 4; s++) \
            *(uint4*)&sA[st][ar0 + s * 4][ac0] = tf4(ra[s]); \
        sW[st][wo0][wq0 + 0] = __float_as_uint(rw0.x); \
        sW[st][wo0][wq0 + 1] = __float_as_uint(rw0.y); \
        sW[st][wo0][wq0 + 2] = __float_as_uint(rw0.z); \
        sW[st][wo0][wq0 + 3] = __float_as_uint(rw0.w); \
    } while (0)

    G3_LOAD(0); G3_STORE(0);
    __syncthreads();
    int cur = 0;
    for (int cc = 0; cc < 128; cc += 16) {
        const bool hasnext = (cc + 16 < 128);
        if (hasnext) G3_LOAD(cc + 16);
        #pragma unroll
        for (int ks = 0; ks < 2; ks++) {
            int k0 = ks * 8;
            uint32_t afr[2][4];
            #pragma unroll
            for (int mt = 0; mt < 2; mt++) {
                int o = obase + mt * 16 + gid;
                afr[mt][0] = sW[cur][o][k0 + tig];
                afr[mt][1] = sW[cur][o + 8][k0 + tig];
                afr[mt][2] = sW[cur][o][k0 + tig + 4];
                afr[mt][3] = sW[cur][o + 8][k0 + tig + 4];
            }
            #pragma unroll
            for (int nt = 0; nt < 8; nt++) {
                uint32_t bfr[2];
                int p = pbase + nt * 8 + gid;
                bfr[0] = sA[cur][k0 + tig][p];
                bfr[1] = sA[cur][k0 + tig + 4][p];
                mma_tf32(acc[0][nt], afr[0], bfr);
                mma_tf32(acc[1][nt], afr[1], bfr);
            }
        }
        if (hasnext) G3_STORE(cur ^ 1);
        __syncthreads();
        cur ^= 1;
    }
    float* ob = out + (size_t)b * 64 * HWSZ;
    #pragma unroll
    for (int mt = 0; mt < 2; mt++) {
        int o1 = obase + mt * 16 + gid;
        float bia = bf[o1], bib = bf[o1 + 8];
        #pragma unroll
        for (int nt = 0; nt < 8; nt++) {
            int p = p0 + pbase + nt * 8 + 2 * tig;
            *(float2*)&ob[(size_t)o1 * HWSZ + p] = make_float2(acc[mt][nt].x + bia, acc[mt][nt].y + bia);
            *(float2*)&ob[(size_t)(o1 + 8) * HWSZ + p] = make_float2(acc[mt][nt].z + bib, acc[mt][nt].w + bib);
        }
    }
}

extern "C" void kernel_launch(void* const* d_in, const int* in_sizes, int n_in,
                              void* d_out, int out_size) {
    const float* x     = (const float*)d_in[0];
    const float* w1    = (const float*)d_in[1];
    const float* b1    = (const float*)d_in[2];
    const float* gamma = (const float*)d_in[3];
    const float* beta  = (const float*)d_in[4];
    const float* w2    = (const float*)d_in[5];
    const float* b2    = (const float*)d_in[6];
    const float* g1    = (const float*)d_in[7];
    const float* gb1   = (const float*)d_in[8];
    const float* g2    = (const float*)d_in[9];
    const float* gb2   = (const float*)d_in[10];
    const float* wf    = (const float*)d_in[11];
    const float* bf    = (const float*)d_in[12];
    float* out = (float*)d_out;

    cudaFuncSetAttribute(k_gemm1, cudaFuncAttributeMaxDynamicSharedMemorySize, G1_SMEM);

    // launch order: k_gemm1 sits at profiled launch index 3
    k_prep<<<128, 256>>>(w1, w2, wf, 0);
    k_prep<<<128, 256>>>(w1, w2, wf, 1);
    k_dwt<<<dim3(17, 512), 256>>>(x);
    k_gemm1<<<dim3(135, 8), 256, G1_SMEM>>>(b1);
    k_small<<<1, 256>>>(g1, gb1, g2, gb2);
    k_gemm2<<<dim3(269, 8), 256>>>(b2, gamma, beta);
    k_idwt<<<dim3(32, 512), 256>>>();
    k_final<<<dim3(256, 8), 256>>>(x, bf, out);
}

// round 9
// speedup vs baseline: 1.2697x; 1.0834x over previous
#include <cuda_runtime.h>
#include <cuda_fp16.h>
#include <stdint.h>
#include <math.h>

#define BB 8
#define CC 64
#define HH 256
#define WW 256
#define OHH 131
#define OWW 131
#define PP (OHH*OWW)      /* 17161 */
#define PSTR 17164        /* fp32 channel stride (mult of 4) */
#define PSTRH 17168       /* fp16 channel stride (mult of 8 -> 16B rows) */
#define HWSZ (HH*WW)      /* 65536 */

// db4 filters
__constant__ float DEC_LO[8] = {
    -0.010597401784997278f, 0.032883011666982945f, 0.030841381835986965f,
    -0.18703481171888114f, -0.02798376941698385f, 0.6308807679295904f,
    0.7148465705525415f, 0.23037781330885523f };
__constant__ float DEC_HI[8] = {
    -0.23037781330885523f, 0.7148465705525415f, -0.6308807679295904f,
    -0.02798376941698385f, 0.18703481171888114f, 0.030841381835986965f,
    -0.032883011666982945f, -0.010597401784997278f };

// Scratch (device globals). Slack for cp.async tail reads.
__device__ __align__(16) __half g_ffh[(size_t)BB*256*PSTRH + 8192]; // coeffs then gated, fp16
__device__ __align__(16) float g_z[(size_t)BB*128*PSTR + 4096];     // z pre-GN fp32
__device__ __align__(16) float g_recon[(size_t)BB*64*HWSZ];
__device__ __align__(16) __half g_w1h[128*256];   // fp16 w1
__device__ __align__(16) float g_w2r[256*128];    // tf32-rounded
__device__ __align__(16) float g_wfr[64*128];
__device__ float g_stats[128];
__device__ float g_density[512];
__device__ float g_munorm[128];
__device__ float g_gates[32];

// ---- helpers ----
__device__ __forceinline__ uint32_t f2tf32(float x) {
    uint32_t r; asm("cvt.rna.tf32.f32 %0, %1;" : "=r"(r) : "f"(x)); return r;
}
__device__ __forceinline__ float rtf(float x) { return __uint_as_float(f2tf32(x)); }
__device__ __forceinline__ void mma_tf32(float4& d, const uint32_t a[4], const uint32_t b[2]) {
    asm volatile("mma.sync.aligned.m16n8k8.row.col.f32.tf32.tf32.f32 "
        "{%0,%1,%2,%3}, {%4,%5,%6,%7}, {%8,%9}, {%0,%1,%2,%3};"
        : "+f"(d.x), "+f"(d.y), "+f"(d.z), "+f"(d.w)
        : "r"(a[0]), "r"(a[1]), "r"(a[2]), "r"(a[3]), "r"(b[0]), "r"(b[1]));
}
__device__ __forceinline__ void mma_f16(float4& d, const uint32_t a[4], uint32_t b0, uint32_t b1) {
    asm volatile("mma.sync.aligned.m16n8k16.row.col.f32.f16.f16.f32 "
        "{%0,%1,%2,%3}, {%4,%5,%6,%7}, {%8,%9}, {%0,%1,%2,%3};"
        : "+f"(d.x), "+f"(d.y), "+f"(d.z), "+f"(d.w)
        : "r"(a[0]), "r"(a[1]), "r"(a[2]), "r"(a[3]), "r"(b0), "r"(b1));
}
__device__ __forceinline__ void ldsm4(uint32_t r[4], uint32_t a) {
    asm volatile("ldmatrix.sync.aligned.m8n8.x4.shared.b16 {%0,%1,%2,%3}, [%4];"
        : "=r"(r[0]), "=r"(r[1]), "=r"(r[2]), "=r"(r[3]) : "r"(a));
}
__device__ __forceinline__ void ldsm4t(uint32_t r[4], uint32_t a) {
    asm volatile("ldmatrix.sync.aligned.m8n8.x4.trans.shared.b16 {%0,%1,%2,%3}, [%4];"
        : "=r"(r[0]), "=r"(r[1]), "=r"(r[2]), "=r"(r[3]) : "r"(a));
}
__device__ __forceinline__ uint4 tf4(float4 v) {
    uint4 u; u.x = f2tf32(v.x); u.y = f2tf32(v.y); u.z = f2tf32(v.z); u.w = f2tf32(v.w);
    return u;
}

// ---------------- K0: prep — weights, zero accumulators ----------------
__global__ void k_prep(const float* __restrict__ w1, const float* __restrict__ w2,
                       const float* __restrict__ wf, int phase) {
    int i = blockIdx.x * 256 + threadIdx.x;     // grid 128 -> 32768
    if (phase == 0) {
        g_w1h[i] = __float2half(w1[i]);
        if (i < 512) g_density[i] = 0.f;
        if (i < 128) g_stats[i] = 0.f;
    } else {
        g_w2r[i] = rtf(w2[i]);
        if (i < 8192) g_wfr[i] = rtf(wf[i]);
    }
}

// ---------------- K2: DWT2 -> g_ffh (fp16) + inline density ----------------
__global__ void __launch_bounds__(256) k_dwt(const float* __restrict__ x) {
    const int gi0 = blockIdx.x * 8;
    const int bc = blockIdx.y;
    __shared__ float sIn[22][272];
    __shared__ float sT[2][22][132];
    const float* xp = x + (size_t)bc * HWSZ;

    int cnt = 0;
    const bool owner = (blockIdx.x < 16);
    for (int idx = threadIdx.x; idx < 22 * 64; idx += 256) {
        int r = idx >> 6, q = idx & 63;
        int m = 2 * gi0 - 6 + r;
        m = (m < 0) ? (-1 - m) : ((m > 255) ? (511 - m) : m);
        float4 v = *(const float4*)&xp[m * 256 + 4 * q];
        *(float4*)&sIn[r][8 + 4 * q] = v;
        if (owner && r >= 6)
            cnt += (v.x != 0.f) + (v.y != 0.f) + (v.z != 0.f) + (v.w != 0.f);
    }
    if (owner) {
        #pragma unroll
        for (int off = 16; off > 0; off >>= 1)
            cnt += __shfl_down_sync(0xffffffffu, cnt, off);
        if ((threadIdx.x & 31) == 0 && cnt > 0)
            atomicAdd(&g_density[bc], (float)cnt);
    }
    for (int idx = threadIdx.x; idx < 22 * 12; idx += 256) {
        int r = idx / 12, e = idx % 12;
        int m = 2 * gi0 - 6 + r;
        m = (m < 0) ? (-1 - m) : ((m > 255) ? (511 - m) : m);
        int col = (e < 6) ? (2 + e) : (258 + e);
        int n = (e < 6) ? (5 - e) : (261 - e);
        sIn[r][col] = xp[m * 256 + n];
    }
    __syncthreads();
    for (int idx = threadIdx.x; idx < 22 * 131; idx += 256) {
        int r = idx / 131, j = idx % 131;
        float lo = 0.f, hi = 0.f;
        #pragma unroll
        for (int v = 0; v < 8; v++) {
            float xv = sIn[r][2 * j + v + 2];
            lo += xv * DEC_LO[7 - v];
            hi += xv * DEC_HI[7 - v];
        }
        sT[0][r][j] = lo; sT[1][r][j] = hi;
    }
    __syncthreads();
    int b = bc >> 6, c = bc & 63;
    __half* base = g_ffh + ((size_t)b * 256 + c) * PSTRH;
    for (int idx = threadIdx.x; idx < 8 * 131; idx += 256) {
        int ii = idx / 131, j = idx % 131;
        int gi = gi0 + ii;
        if (gi < OHH) {
            float aa = 0.f, da = 0.f, ad = 0.f, dd = 0.f;
            #pragma unroll
            for (int u = 0; u < 8; u++) {
                float tl = sT[0][2 * ii + u][j], th = sT[1][2 * ii + u][j];
                float gl = DEC_LO[7 - u], gh = DEC_HI[7 - u];
                aa += gl * tl; da += gh * tl; ad += gl * th; dd += gh * th;
            }
            int p = gi * OWW + j;
            base[p] = __float2half(aa);
            base[(size_t)64 * PSTRH + p] = __float2half(da);
            base[(size_t)128 * PSTRH + p] = __float2half(ad);
            base[(size_t)192 * PSTRH + p] = __float2half(dd);
        }
    }
}

// ---------------- K3: z = ff @ w1^T + b1 (fp16 mma + ldmatrix, cp.async 4-stage) ----------------
#define G1_STAGES 4
#define G1_SAH 2176   /* 16*136 halfs */
#define G1_SWH 3072   /* 128*24 halfs */

__global__ void __launch_bounds__(256) k_gemm1(const float* __restrict__ b1) {
    __shared__ __half sA[G1_STAGES][16][136];
    __shared__ __half sW[G1_STAGES][128][24];
    const int b = blockIdx.y;
    const int p0 = blockIdx.x * 128;
    const int tid = threadIdx.x;
    const __half* ffb = g_ffh + (size_t)b * 256 * PSTRH;
    uint32_t saddrA = (uint32_t)__cvta_generic_to_shared(&sA[0][0][0]);
    uint32_t saddrW = (uint32_t)__cvta_generic_to_shared(&sW[0][0][0]);

    const int ar_ = tid >> 4, ac8 = (tid & 15) * 8;   // A tile: 16 rows x 16 chunks
    const int wo_ = tid >> 1, wk8 = (tid & 1) * 8;    // W tile: 128 rows x 2 chunks

    #define G1_ISSUE(stage, qc) do { \
        const __half* srcA = ffb + (size_t)((qc) + ar_) * PSTRH + p0 + ac8; \
        uint32_t dstA = saddrA + (uint32_t)(((stage) * G1_SAH + ar_ * 136 + ac8) * 2); \
        int rem = PP - (p0 + ac8); \
        int bytes = (rem >= 8) ? 16 : ((rem > 0) ? rem * 2 : 0); \
        asm volatile("cp.async.ca.shared.global [%0], [%1], 16, %2;" \
                     :: "r"(dstA), "l"(srcA), "r"(bytes)); \
        const __half* srcW = g_w1h + wo_ * 256 + (qc) + wk8; \
        uint32_t dstW = saddrW + (uint32_t)(((stage) * G1_SWH + wo_ * 24 + wk8) * 2); \
        asm volatile("cp.async.ca.shared.global [%0], [%1], 16;" \
                     :: "r"(dstW), "l"(srcW)); \
    } while (0)

    G1_ISSUE(0, 0);   asm volatile("cp.async.commit_group;" ::: "memory");
    G1_ISSUE(1, 16);  asm volatile("cp.async.commit_group;" ::: "memory");
    G1_ISSUE(2, 32);  asm volatile("cp.async.commit_group;" ::: "memory");

    const int w = tid >> 5, lane = tid & 31;
    const int gid = lane >> 2, tig = lane & 3;
    const int obase = (w >> 1) * 32, pbase = (w & 1) * 64;
    const int q = lane >> 3, r = lane & 7;
    // ldmatrix per-lane byte offsets (within a stage)
    const uint32_t aoff = (uint32_t)((((q & 1) * 8 + r) * 136 + (q >> 1) * 8) * 2);
    const uint32_t woff0 = (uint32_t)(((obase + (q & 1) * 8 + r) * 24 + (q >> 1) * 8) * 2);
    const uint32_t woff1 = woff0 + 16 * 24 * 2;
    float4 acc[2][8] = {};
    const bool fullA = (p0 + 128 <= PP);

    for (int i = 0; i < 16; i++) {
        asm volatile("cp.async.wait_group 2;" ::: "memory");
        __syncthreads();
        if (i + 3 < 16) { G1_ISSUE((i + 3) & 3, (i + 3) * 16); }
        asm volatile("cp.async.commit_group;" ::: "memory");
        uint32_t baA = saddrA + (uint32_t)((i & 3) * G1_SAH * 2);
        uint32_t baW = saddrW + (uint32_t)((i & 3) * G1_SWH * 2);
        uint32_t wa0[4], wa1[4];
        ldsm4(wa0, baW + woff0);
        ldsm4(wa1, baW + woff1);
        #pragma unroll
        for (int j = 0; j < 4; j++) {
            uint32_t ab[4];
            ldsm4t(ab, baA + aoff + (uint32_t)((pbase + j * 16) * 2));
            mma_f16(acc[0][2 * j],     wa0, ab[0], ab[1]);
            mma_f16(acc[1][2 * j],     wa1, ab[0], ab[1]);
            mma_f16(acc[0][2 * j + 1], wa0, ab[2], ab[3]);
            mma_f16(acc[1][2 * j + 1], wa1, ab[2], ab[3]);
        }
    }
    // epilogue: +bias, store z fp32, GN stats
    float s1[2] = {0.f, 0.f}, s2[2] = {0.f, 0.f};
    float* zb = g_z + (size_t)b * 128 * PSTR;
    #pragma unroll
    for (int mt = 0; mt < 2; mt++) {
        int o1 = obase + mt * 16 + gid;
        float bia = b1[o1], bib = b1[o1 + 8];
        #pragma unroll
        for (int nt = 0; nt < 8; nt++) {
            int p = p0 + pbase + nt * 8 + 2 * tig;
            float vx = acc[mt][nt].x + bia, vy = acc[mt][nt].y + bia;
            float vz = acc[mt][nt].z + bib, vw = acc[mt][nt].w + bib;
            if (fullA) {
                s1[mt] += vx + vy + vz + vw;
                s2[mt] += vx*vx + vy*vy + vz*vz + vw*vw;
                *(float2*)&zb[(size_t)o1 * PSTR + p] = make_float2(vx, vy);
                *(float2*)&zb[(size_t)(o1 + 8) * PSTR + p] = make_float2(vz, vw);
            } else {
                if (p < PP)     { zb[(size_t)o1*PSTR + p] = vx;       zb[(size_t)(o1+8)*PSTR + p] = vz;       s1[mt] += vx + vz; s2[mt] += vx*vx + vz*vz; }
                if (p + 1 < PP) { zb[(size_t)o1*PSTR + p + 1] = vy;   zb[(size_t)(o1+8)*PSTR + p + 1] = vw;   s1[mt] += vy + vw; s2[mt] += vy*vy + vw*vw; }
            }
        }
    }
    #pragma unroll
    for (int off = 16; off > 0; off >>= 1) {
        s1[0] += __shfl_down_sync(0xffffffffu, s1[0], off);
        s2[0] += __shfl_down_sync(0xffffffffu, s2[0], off);
        s1[1] += __shfl_down_sync(0xffffffffu, s1[1], off);
        s2[1] += __shfl_down_sync(0xffffffffu, s2[1], off);
    }
    if (lane == 0) {
        int g0 = (w >> 1) * 2;
        atomicAdd(&g_stats[(b * 8 + g0) * 2],     s1[0]);
        atomicAdd(&g_stats[(b * 8 + g0) * 2 + 1], s2[0]);
        atomicAdd(&g_stats[(b * 8 + g0 + 1) * 2],     s1[1]);
        atomicAdd(&g_stats[(b * 8 + g0 + 1) * 2 + 1], s2[1]);
    }
}

// ---------------- K4: finalize stats + gates ----------------
__global__ void k_small(const float* __restrict__ g1, const float* __restrict__ gb1,
                        const float* __restrict__ g2, const float* __restrict__ gb2) {
    int t = threadIdx.x;
    if (t < 64) {
        float s1 = g_stats[2 * t], s2 = g_stats[2 * t + 1];
        float invN = 1.f / (16.f * (float)PP);
        float mu = s1 * invN;
        float var = s2 * invN - mu * mu;
        g_munorm[2 * t] = mu;
        g_munorm[2 * t + 1] = rsqrtf(var + 1e-5f);
    }
    __shared__ float sh[8][16];
    int w = t >> 5, lane = t & 31;
    const float invHW = 1.f / (float)HWSZ;
    if (lane < 16) {
        float s = gb1[lane];
        #pragma unroll 4
        for (int c = 0; c < 64; c++) s += (g_density[w * 64 + c] * invHW) * g1[lane * 64 + c];
        sh[w][lane] = fmaxf(s, 0.f);
    }
    __syncwarp();
    if (lane < 4) {
        float s = gb2[lane];
        #pragma unroll
        for (int i = 0; i < 16; i++) s += sh[w][i] * g2[lane * 16 + i];
        g_gates[w * 4 + lane] = 1.f / (1.f + expf(-s));
    }
}

// ---------------- K5: gated = (gelu(GN(z)) @ w2^T + b2) * gate ----------------
__global__ void __launch_bounds__(256) k_gemm2(const float* __restrict__ b2,
                                               const float* __restrict__ gamma,
                                               const float* __restrict__ beta) {
    const int b = blockIdx.y;
    const int p0 = blockIdx.x * 64;
    __shared__ uint32_t sWt[2][16][260];
    __shared__ uint32_t sA[2][16][72];
    __shared__ float sScale[128], sShift[128];
    const int tid = threadIdx.x;
    if (tid < 128) {
        int qq = tid, g = qq >> 4;
        float mu = g_munorm[(b * 8 + g) * 2];
        float rs = g_munorm[(b * 8 + g) * 2 + 1];
        float sc = rs * gamma[qq];
        sScale[qq] = sc;
        sShift[qq] = beta[qq] - mu * sc;
    }
    __syncthreads();
    const int w = tid >> 5, lane = tid & 31;
    const int gid = lane >> 2, tig = lane & 3;
    const int obase = (w >> 1) * 64, pbase = (w & 1) * 32;
    float4 acc[4][4] = {};
    const float* zb = g_z + (size_t)b * 128 * PSTR;
    const bool fullA = (p0 + 64 <= PP);

    const int ar = tid >> 4, ac = (tid & 15) * 4;
    const int wo = tid >> 2, wq = (tid & 3) * 4;
    float4 ra, rw[4];

    #define G2_LOAD(qc) do { \
        if (fullA) { \
            ra = *(const float4*)&zb[(size_t)((qc) + ar) * PSTR + p0 + ac]; \
        } else { \
            const float* rp = &zb[(size_t)((qc) + ar) * PSTR]; \
            ra.x = (p0+ac   < PP) ? rp[p0+ac]   : 0.f; \
            ra.y = (p0+ac+1 < PP) ? rp[p0+ac+1] : 0.f; \
            ra.z = (p0+ac+2 < PP) ? rp[p0+ac+2] : 0.f; \
            ra.w = (p0+ac+3 < PP) ? rp[p0+ac+3] : 0.f; \
        } \
        _Pragma("unroll") \
        for (int s = 0; s < 4; s++) \
            rw[s] = *(const float4*)&g_w2r[(wo + s * 64) * 128 + (qc) + wq]; \
    } while (0)
    #define GELU4(v, row) do { \
        float sc_ = sScale[row], sh_ = sShift[row]; \
        v.x = v.x * sc_ + sh_; v.x = 0.5f * v.x * (1.f + erff(v.x * 0.70710678118654752f)); \
        v.y = v.y * sc_ + sh_; v.y = 0.5f * v.y * (1.f + erff(v.y * 0.70710678118654752f)); \
        v.z = v.z * sc_ + sh_; v.z = 0.5f * v.z * (1.f + erff(v.z * 0.70710678118654752f)); \
        v.w = v.w * sc_ + sh_; v.w = 0.5f * v.w * (1.f + erff(v.w * 0.70710678118654752f)); \
    } while (0)
    #define G2_STORE(st, qc) do { \
        GELU4(ra, (qc) + ar); \
        *(uint4*)&sA[st][ar][ac] = tf4(ra); \
        _Pragma("unroll") \
        for (int s = 0; s < 4; s++) { \
            sWt[st][wq + 0][wo + s * 64] = __float_as_uint(rw[s].x); \
            sWt[st][wq + 1][wo + s * 64] = __float_as_uint(rw[s].y); \
            sWt[st][wq + 2][wo + s * 64] = __float_as_uint(rw[s].z); \
            sWt[st][wq + 3][wo + s * 64] = __float_as_uint(rw[s].w); \
        } \
    } while (0)

    G2_LOAD(0); G2_STORE(0, 0);
    __syncthreads();
    int cur = 0;
    for (int qc = 0; qc < 128; qc += 16) {
        const bool hasnext = (qc + 16 < 128);
        if (hasnext) G2_LOAD(qc + 16);
        #pragma unroll
        for (int ks = 0; ks < 2; ks++) {
            int k0 = ks * 8;
            uint32_t afr[4][4];
            #pragma unroll
            for (int mt = 0; mt < 4; mt++) {
                int o = obase + mt * 16 + gid;
                afr[mt][0] = sWt[cur][k0 + tig][o];
                afr[mt][1] = sWt[cur][k0 + tig][o + 8];
                afr[mt][2] = sWt[cur][k0 + tig + 4][o];
                afr[mt][3] = sWt[cur][k0 + tig + 4][o + 8];
            }
            #pragma unroll
            for (int nt = 0; nt < 4; nt++) {
                uint32_t bfr[2];
                int p = pbase + nt * 8 + gid;
                bfr[0] = sA[cur][k0 + tig][p];
                bfr[1] = sA[cur][k0 + tig + 4][p];
                #pragma unroll
                for (int mt = 0; mt < 4; mt++)
                    mma_tf32(acc[mt][nt], afr[mt], bfr);
            }
        }
        if (hasnext) G2_STORE(cur ^ 1, qc + 16);
        __syncthreads();
        cur ^= 1;
    }
    __half* gbuf = g_ffh + (size_t)b * 256 * PSTRH;
    #pragma unroll
    for (int mt = 0; mt < 4; mt++) {
        int o1 = obase + mt * 16 + gid;
        float ga = g_gates[b * 4 + (o1 >> 6)];
        float gb_ = g_gates[b * 4 + ((o1 + 8) >> 6)];
        float bia = b2[o1], bib = b2[o1 + 8];
        #pragma unroll
        for (int nt = 0; nt < 4; nt++) {
            int p = p0 + pbase + nt * 8 + 2 * tig;
            float vx = (acc[mt][nt].x + bia) * ga, vy = (acc[mt][nt].y + bia) * ga;
            float vz = (acc[mt][nt].z + bib) * gb_, vw = (acc[mt][nt].w + bib) * gb_;
            if (fullA) {
                *(__half2*)&gbuf[(size_t)o1 * PSTRH + p] = __floats2half2_rn(vx, vy);
                *(__half2*)&gbuf[(size_t)(o1 + 8) * PSTRH + p] = __floats2half2_rn(vz, vw);
            } else {
                if (p < PP)     { gbuf[(size_t)o1*PSTRH + p] = __float2half_rn(vx);     gbuf[(size_t)(o1+8)*PSTRH + p] = __float2half_rn(vz); }
                if (p + 1 < PP) { gbuf[(size_t)o1*PSTRH + p + 1] = __float2half_rn(vy); gbuf[(size_t)(o1+8)*PSTRH + p + 1] = __float2half_rn(vw); }
            }
        }
    }
}

// ---------------- K6: IDWT2 -> g_recon (reads fp16 gated) ----------------
__global__ void __launch_bounds__(256) k_idwt() {
    int tile = blockIdx.x;
    int bc = blockIdx.y;
    int h0 = (tile >> 2) * 32;
    int w0 = (tile & 3) * 64;
    int b = bc >> 6, c = bc & 63;
    __shared__ float scoef[4][19][36];
    __shared__ float stmp[4][19][68];
    const __half* gb = g_ffh + ((size_t)b * 256 + c) * PSTRH;
    int ib0 = h0 >> 1, jb0 = w0 >> 1;

    for (int idx = threadIdx.x; idx < 4 * 19 * 35; idx += 256) {
        int k = idx / (19 * 35); int rem = idx % (19 * 35);
        int il = rem / 35, jl = rem % 35;
        scoef[k][il][jl] = __half2float(gb[(size_t)k * 64 * PSTRH + (ib0 + il) * OWW + jb0 + jl]);
    }
    __syncthreads();
    for (int s = threadIdx.x; s < 19 * 16; s += 256) {
        int il = s >> 4, ws = s & 15;
        int wl = ws * 4, jb = wl >> 1;
        #pragma unroll
        for (int k = 0; k < 4; k++) {
            const float* fc = (k < 2) ? DEC_LO : DEC_HI;
            float c0 = scoef[k][il][jb],     c1 = scoef[k][il][jb + 1];
            float c2 = scoef[k][il][jb + 2], c3 = scoef[k][il][jb + 3];
            float c4 = scoef[k][il][jb + 4];
            stmp[k][il][wl + 0] = c0*fc[1] + c1*fc[3] + c2*fc[5] + c3*fc[7];
            stmp[k][il][wl + 1] = c0*fc[0] + c1*fc[2] + c2*fc[4] + c3*fc[6];
            stmp[k][il][wl + 2] = c1*fc[1] + c2*fc[3] + c3*fc[5] + c4*fc[7];
            stmp[k][il][wl + 3] = c1*fc[0] + c2*fc[2] + c3*fc[4] + c4*fc[6];
        }
    }
    __syncthreads();
    float* rb = g_recon + ((size_t)b * 64 + c) * HWSZ;
    for (int s = threadIdx.x; s < 512; s += 256) {
        int wlh = s & 63, hs = s >> 6;
        int hb = hs * 4, ib = hb >> 1;
        float t[4][5];
        #pragma unroll
        for (int k = 0; k < 4; k++)
            #pragma unroll
            for (int m = 0; m < 5; m++)
                t[k][m] = stmp[k][ib + m][wlh];
        #pragma unroll
        for (int dh = 0; dh < 4; dh++) {
            int sh = dh >> 1;
            float acc = 0.f;
            #pragma unroll
            for (int k = 0; k < 4; k++) {
                const float* fr = (k & 1) ? DEC_HI : DEC_LO;
                if (dh & 1)
                    acc += t[k][sh]*fr[0] + t[k][sh+1]*fr[2] + t[k][sh+2]*fr[4] + t[k][sh+3]*fr[6];
                else
                    acc += t[k][sh]*fr[1] + t[k][sh+1]*fr[3] + t[k][sh+2]*fr[5] + t[k][sh+3]*fr[7];
            }
            rb[(h0 + hb + dh) * WW + w0 + wlh] = acc;
        }
    }
}

// ---------------- K7: fused = [x, recon] @ wf^T + bf (tf32, pipelined) ----------------
__global__ void __launch_bounds__(256) k_final(const float* __restrict__ x,
                                               const float* __restrict__ bf,
                                               float* __restrict__ out) {
    const int b = blockIdx.y;
    const int p0 = blockIdx.x * 256;
    __shared__ uint32_t sW[2][64][20];
    __shared__ uint32_t sA[2][16][264];
    const int tid = threadIdx.x;
    const int w = tid >> 5, lane = tid & 31;
    const int gid = lane >> 2, tig = lane & 3;
    const int obase = (w >> 2) * 32, pbase = (w & 3) * 64;
    float4 acc[2][8] = {};
    const float* xb = x + (size_t)b * 64 * HWSZ;
    const float* rb = g_recon + (size_t)b * 64 * HWSZ;

    const int ar0 = tid >> 6;
    const int ac0 = (tid & 63) * 4;
    const int wo0 = tid >> 2, wq0 = (tid & 3) * 4;
    float4 ra[4], rw0;

    #define G3_LOAD(cc) do { \
        _Pragma("unroll") \
        for (int s = 0; s < 4; s++) { \
            int ch = (cc) + ar0 + s * 4; \
            const float* src = (ch < 64) ? &xb[(size_t)ch * HWSZ] : &rb[(size_t)(ch - 64) * HWSZ]; \
            ra[s] = *(const float4*)&src[p0 + ac0]; \
        } \
        rw0 = *(const float4*)&g_wfr[wo0 * 128 + (cc) + wq0]; \
    } while (0)
    #define G3_STORE(st) do { \
        _Pragma("unroll") \
        for (int s = 0; s < 4; s++) \
            *(uint4*)&sA[st][ar0 + s * 4][ac0] = tf4(ra[s]); \
        sW[st][wo0][wq0 + 0] = __float_as_uint(rw0.x); \
        sW[st][wo0][wq0 + 1] = __float_as_uint(rw0.y); \
        sW[st][wo0][wq0 + 2] = __float_as_uint(rw0.z); \
        sW[st][wo0][wq0 + 3] = __float_as_uint(rw0.w); \
    } while (0)

    G3_LOAD(0); G3_STORE(0);
    __syncthreads();
    int cur = 0;
    for (int cc = 0; cc < 128; cc += 16) {
        const bool hasnext = (cc + 16 < 128);
        if (hasnext) G3_LOAD(cc + 16);
        #pragma unroll
        for (int ks = 0; ks < 2; ks++) {
            int k0 = ks * 8;
            uint32_t afr[2][4];
            #pragma unroll
            for (int mt = 0; mt < 2; mt++) {
                int o = obase + mt * 16 + gid;
                afr[mt][0] = sW[cur][o][k0 + tig];
                afr[mt][1] = sW[cur][o + 8][k0 + tig];
                afr[mt][2] = sW[cur][o][k0 + tig + 4];
                afr[mt][3] = sW[cur][o + 8][k0 + tig + 4];
            }
            #pragma unroll
            for (int nt = 0; nt < 8; nt++) {
                uint32_t bfr[2];
                int p = pbase + nt * 8 + gid;
                bfr[0] = sA[cur][k0 + tig][p];
                bfr[1] = sA[cur][k0 + tig + 4][p];
                mma_tf32(acc[0][nt], afr[0], bfr);
                mma_tf32(acc[1][nt], afr[1], bfr);
            }
        }
        if (hasnext) G3_STORE(cur ^ 1);
        __syncthreads();
        cur ^= 1;
    }
    float* ob = out + (size_t)b * 64 * HWSZ;
    #pragma unroll
    for (int mt = 0; mt < 2; mt++) {
        int o1 = obase + mt * 16 + gid;
        float bia = bf[o1], bib = bf[o1 + 8];
        #pragma unroll
        for (int nt = 0; nt < 8; nt++) {
            int p = p0 + pbase + nt * 8 + 2 * tig;
            *(float2*)&ob[(size_t)o1 * HWSZ + p] = make_float2(acc[mt][nt].x + bia, acc[mt][nt].y + bia);
            *(float2*)&ob[(size_t)(o1 + 8) * HWSZ + p] = make_float2(acc[mt][nt].z + bib, acc[mt][nt].w + bib);
        }
    }
}

extern "C" void kernel_launch(void* const* d_in, const int* in_sizes, int n_in,
                              void* d_out, int out_size) {
    const float* x     = (const float*)d_in[0];
    const float* w1    = (const float*)d_in[1];
    const float* b1    = (const float*)d_in[2];
    const float* gamma = (const float*)d_in[3];
    const float* beta  = (const float*)d_in[4];
    const float* w2    = (const float*)d_in[5];
    const float* b2    = (const float*)d_in[6];
    const float* g1    = (const float*)d_in[7];
    const float* gb1   = (const float*)d_in[8];
    const float* g2    = (const float*)d_in[9];
    const float* gb2   = (const float*)d_in[10];
    const float* wf    = (const float*)d_in[11];
    const float* bf    = (const float*)d_in[12];
    float* out = (float*)d_out;

    // launch order: k_gemm1 sits at profiled launch index 3
    k_prep<<<128, 256>>>(w1, w2, wf, 0);
    k_prep<<<128, 256>>>(w1, w2, wf, 1);
    k_dwt<<<dim3(17, 512), 256>>>(x);
    k_gemm1<<<dim3(135, 8), 256>>>(b1);
    k_small<<<1, 256>>>(g1, gb1, g2, gb2);
    k_gemm2<<<dim3(269, 8), 256>>>(b2, gamma, beta);
    k_idwt<<<dim3(32, 512), 256>>>();
    k_final<<<dim3(256, 8), 256>>>(x, bf, out);
}

// round 10
// speedup vs baseline: 1.3314x; 1.0486x over previous
#include <cuda_runtime.h>
#include <cuda_fp16.h>
#include <stdint.h>
#include <math.h>

#define BB 8
#define CC 64
#define HH 256
#define WW 256
#define OHH 131
#define OWW 131
#define PP (OHH*OWW)      /* 17161 */
#define PSTR 17164        /* fp32 channel stride */
#define PSTRH 17168       /* fp16 channel stride (16B rows) */
#define HWSZ (HH*WW)

// db4 filters
__constant__ float DEC_LO[8] = {
    -0.010597401784997278f, 0.032883011666982945f, 0.030841381835986965f,
    -0.18703481171888114f, -0.02798376941698385f, 0.6308807679295904f,
    0.7148465705525415f, 0.23037781330885523f };
__constant__ float DEC_HI[8] = {
    -0.23037781330885523f, 0.7148465705525415f, -0.6308807679295904f,
    -0.02798376941698385f, 0.18703481171888114f, 0.030841381835986965f,
    -0.032883011666982945f, -0.010597401784997278f };

// Scratch
__device__ __align__(16) __half g_ffh[(size_t)BB*256*PSTRH + 8192];
__device__ __align__(16) float g_z[(size_t)BB*128*PSTR + 4096];
__device__ __align__(16) __half g_reconh[(size_t)BB*64*HWSZ];
__device__ __align__(16) __half g_w1h[128*256];
__device__ __align__(16) __half g_w2h[256*128];
__device__ __align__(16) __half g_wfh[64*128];
__device__ float g_stats[128];
__device__ float g_density[512];
__device__ float g_munorm[128];
__device__ float g_gates[32];

// ---- helpers ----
__device__ __forceinline__ void mma_f16(float4& d, const uint32_t a[4], uint32_t b0, uint32_t b1) {
    asm volatile("mma.sync.aligned.m16n8k16.row.col.f32.f16.f16.f32 "
        "{%0,%1,%2,%3}, {%4,%5,%6,%7}, {%8,%9}, {%0,%1,%2,%3};"
        : "+f"(d.x), "+f"(d.y), "+f"(d.z), "+f"(d.w)
        : "r"(a[0]), "r"(a[1]), "r"(a[2]), "r"(a[3]), "r"(b0), "r"(b1));
}
__device__ __forceinline__ void ldsm4(uint32_t r[4], uint32_t a) {
    asm volatile("ldmatrix.sync.aligned.m8n8.x4.shared.b16 {%0,%1,%2,%3}, [%4];"
        : "=r"(r[0]), "=r"(r[1]), "=r"(r[2]), "=r"(r[3]) : "r"(a));
}
__device__ __forceinline__ void ldsm4t(uint32_t r[4], uint32_t a) {
    asm volatile("ldmatrix.sync.aligned.m8n8.x4.trans.shared.b16 {%0,%1,%2,%3}, [%4];"
        : "=r"(r[0]), "=r"(r[1]), "=r"(r[2]), "=r"(r[3]) : "r"(a));
}
__device__ __forceinline__ uint32_t packh2(float a, float b) {
    __half2 h = __floats2half2_rn(a, b);
    return *(uint32_t*)&h;
}

// ---------------- K0: prep ----------------
__global__ void k_prep(const float* __restrict__ w1, const float* __restrict__ w2,
                       const float* __restrict__ wf, int phase) {
    int i = blockIdx.x * 256 + threadIdx.x;     // 32768
    if (phase == 0) {
        g_w1h[i] = __float2half(w1[i]);
        if (i < 512) g_density[i] = 0.f;
        if (i < 128) g_stats[i] = 0.f;
    } else {
        g_w2h[i] = __float2half(w2[i]);
        if (i < 8192) g_wfh[i] = __float2half(wf[i]);
    }
}

// ---------------- K2: DWT2 -> g_ffh + inline density ----------------
__global__ void __launch_bounds__(256) k_dwt(const float* __restrict__ x) {
    const int gi0 = blockIdx.x * 8;
    const int bc = blockIdx.y;
    __shared__ float sIn[22][272];
    __shared__ float sT[2][22][132];
    const float* xp = x + (size_t)bc * HWSZ;

    int cnt = 0;
    const bool owner = (blockIdx.x < 16);
    for (int idx = threadIdx.x; idx < 22 * 64; idx += 256) {
        int r = idx >> 6, q = idx & 63;
        int m = 2 * gi0 - 6 + r;
        m = (m < 0) ? (-1 - m) : ((m > 255) ? (511 - m) : m);
        float4 v = *(const float4*)&xp[m * 256 + 4 * q];
        *(float4*)&sIn[r][8 + 4 * q] = v;
        if (owner && r >= 6)
            cnt += (v.x != 0.f) + (v.y != 0.f) + (v.z != 0.f) + (v.w != 0.f);
    }
    if (owner) {
        #pragma unroll
        for (int off = 16; off > 0; off >>= 1)
            cnt += __shfl_down_sync(0xffffffffu, cnt, off);
        if ((threadIdx.x & 31) == 0 && cnt > 0)
            atomicAdd(&g_density[bc], (float)cnt);
    }
    for (int idx = threadIdx.x; idx < 22 * 12; idx += 256) {
        int r = idx / 12, e = idx % 12;
        int m = 2 * gi0 - 6 + r;
        m = (m < 0) ? (-1 - m) : ((m > 255) ? (511 - m) : m);
        int col = (e < 6) ? (2 + e) : (258 + e);
        int n = (e < 6) ? (5 - e) : (261 - e);
        sIn[r][col] = xp[m * 256 + n];
    }
    __syncthreads();
    for (int idx = threadIdx.x; idx < 22 * 131; idx += 256) {
        int r = idx / 131, j = idx % 131;
        float lo = 0.f, hi = 0.f;
        #pragma unroll
        for (int v = 0; v < 8; v++) {
            float xv = sIn[r][2 * j + v + 2];
            lo += xv * DEC_LO[7 - v];
            hi += xv * DEC_HI[7 - v];
        }
        sT[0][r][j] = lo; sT[1][r][j] = hi;
    }
    __syncthreads();
    int b = bc >> 6, c = bc & 63;
    __half* base = g_ffh + ((size_t)b * 256 + c) * PSTRH;
    for (int idx = threadIdx.x; idx < 8 * 131; idx += 256) {
        int ii = idx / 131, j = idx % 131;
        int gi = gi0 + ii;
        if (gi < OHH) {
            float aa = 0.f, da = 0.f, ad = 0.f, dd = 0.f;
            #pragma unroll
            for (int u = 0; u < 8; u++) {
                float tl = sT[0][2 * ii + u][j], th = sT[1][2 * ii + u][j];
                float gl = DEC_LO[7 - u], gh = DEC_HI[7 - u];
                aa += gl * tl; da += gh * tl; ad += gl * th; dd += gh * th;
            }
            int p = gi * OWW + j;
            base[p] = __float2half(aa);
            base[(size_t)64 * PSTRH + p] = __float2half(da);
            base[(size_t)128 * PSTRH + p] = __float2half(ad);
            base[(size_t)192 * PSTRH + p] = __float2half(dd);
        }
    }
}

// ---------------- K3: gemm1 (fp16 mma + ldmatrix, cp.async 4-stage) ----------------
#define G1_STAGES 4
#define G1_SAH 2176
#define G1_SWH 3072

__global__ void __launch_bounds__(256) k_gemm1(const float* __restrict__ b1) {
    __shared__ __half sA[G1_STAGES][16][136];
    __shared__ __half sW[G1_STAGES][128][24];
    const int b = blockIdx.y;
    const int p0 = blockIdx.x * 128;
    const int tid = threadIdx.x;
    const __half* ffb = g_ffh + (size_t)b * 256 * PSTRH;
    uint32_t saddrA = (uint32_t)__cvta_generic_to_shared(&sA[0][0][0]);
    uint32_t saddrW = (uint32_t)__cvta_generic_to_shared(&sW[0][0][0]);

    const int ar_ = tid >> 4, ac8 = (tid & 15) * 8;
    const int wo_ = tid >> 1, wk8 = (tid & 1) * 8;

    #define G1_ISSUE(stage, qc) do { \
        const __half* srcA = ffb + (size_t)((qc) + ar_) * PSTRH + p0 + ac8; \
        uint32_t dstA = saddrA + (uint32_t)(((stage) * G1_SAH + ar_ * 136 + ac8) * 2); \
        int rem = PP - (p0 + ac8); \
        int bytes = (rem >= 8) ? 16 : ((rem > 0) ? rem * 2 : 0); \
        asm volatile("cp.async.ca.shared.global [%0], [%1], 16, %2;" \
                     :: "r"(dstA), "l"(srcA), "r"(bytes)); \
        const __half* srcW = g_w1h + wo_ * 256 + (qc) + wk8; \
        uint32_t dstW = saddrW + (uint32_t)(((stage) * G1_SWH + wo_ * 24 + wk8) * 2); \
        asm volatile("cp.async.ca.shared.global [%0], [%1], 16;" \
                     :: "r"(dstW), "l"(srcW)); \
    } while (0)

    G1_ISSUE(0, 0);   asm volatile("cp.async.commit_group;" ::: "memory");
    G1_ISSUE(1, 16);  asm volatile("cp.async.commit_group;" ::: "memory");
    G1_ISSUE(2, 32);  asm volatile("cp.async.commit_group;" ::: "memory");

    const int w = tid >> 5, lane = tid & 31;
    const int gid = lane >> 2, tig = lane & 3;
    const int obase = (w >> 1) * 32, pbase = (w & 1) * 64;
    const int q = lane >> 3, r = lane & 7;
    const uint32_t aoff = (uint32_t)((((q & 1) * 8 + r) * 136 + (q >> 1) * 8) * 2);
    const uint32_t woff0 = (uint32_t)(((obase + (q & 1) * 8 + r) * 24 + (q >> 1) * 8) * 2);
    const uint32_t woff1 = woff0 + 16 * 24 * 2;
    float4 acc[2][8] = {};
    const bool fullA = (p0 + 128 <= PP);

    for (int i = 0; i < 16; i++) {
        asm volatile("cp.async.wait_group 2;" ::: "memory");
        __syncthreads();
        if (i + 3 < 16) { G1_ISSUE((i + 3) & 3, (i + 3) * 16); }
        asm volatile("cp.async.commit_group;" ::: "memory");
        uint32_t baA = saddrA + (uint32_t)((i & 3) * G1_SAH * 2);
        uint32_t baW = saddrW + (uint32_t)((i & 3) * G1_SWH * 2);
        uint32_t wa0[4], wa1[4];
        ldsm4(wa0, baW + woff0);
        ldsm4(wa1, baW + woff1);
        #pragma unroll
        for (int j = 0; j < 4; j++) {
            uint32_t ab[4];
            ldsm4t(ab, baA + aoff + (uint32_t)((pbase + j * 16) * 2));
            mma_f16(acc[0][2 * j],     wa0, ab[0], ab[1]);
            mma_f16(acc[1][2 * j],     wa1, ab[0], ab[1]);
            mma_f16(acc[0][2 * j + 1], wa0, ab[2], ab[3]);
            mma_f16(acc[1][2 * j + 1], wa1, ab[2], ab[3]);
        }
    }
    float s1[2] = {0.f, 0.f}, s2[2] = {0.f, 0.f};
    float* zb = g_z + (size_t)b * 128 * PSTR;
    #pragma unroll
    for (int mt = 0; mt < 2; mt++) {
        int o1 = obase + mt * 16 + gid;
        float bia = b1[o1], bib = b1[o1 + 8];
        #pragma unroll
        for (int nt = 0; nt < 8; nt++) {
            int p = p0 + pbase + nt * 8 + 2 * tig;
            float vx = acc[mt][nt].x + bia, vy = acc[mt][nt].y + bia;
            float vz = acc[mt][nt].z + bib, vw = acc[mt][nt].w + bib;
            if (fullA) {
                s1[mt] += vx + vy + vz + vw;
                s2[mt] += vx*vx + vy*vy + vz*vz + vw*vw;
                *(float2*)&zb[(size_t)o1 * PSTR + p] = make_float2(vx, vy);
                *(float2*)&zb[(size_t)(o1 + 8) * PSTR + p] = make_float2(vz, vw);
            } else {
                if (p < PP)     { zb[(size_t)o1*PSTR + p] = vx;       zb[(size_t)(o1+8)*PSTR + p] = vz;       s1[mt] += vx + vz; s2[mt] += vx*vx + vz*vz; }
                if (p + 1 < PP) { zb[(size_t)o1*PSTR + p + 1] = vy;   zb[(size_t)(o1+8)*PSTR + p + 1] = vw;   s1[mt] += vy + vw; s2[mt] += vy*vy + vw*vw; }
            }
        }
    }
    #pragma unroll
    for (int off = 16; off > 0; off >>= 1) {
        s1[0] += __shfl_down_sync(0xffffffffu, s1[0], off);
        s2[0] += __shfl_down_sync(0xffffffffu, s2[0], off);
        s1[1] += __shfl_down_sync(0xffffffffu, s1[1], off);
        s2[1] += __shfl_down_sync(0xffffffffu, s2[1], off);
    }
    if (lane == 0) {
        int g0 = (w >> 1) * 2;
        atomicAdd(&g_stats[(b * 8 + g0) * 2],     s1[0]);
        atomicAdd(&g_stats[(b * 8 + g0) * 2 + 1], s2[0]);
        atomicAdd(&g_stats[(b * 8 + g0 + 1) * 2],     s1[1]);
        atomicAdd(&g_stats[(b * 8 + g0 + 1) * 2 + 1], s2[1]);
    }
}

// ---------------- K4: finalize stats + gates ----------------
__global__ void k_small(const float* __restrict__ g1, const float* __restrict__ gb1,
                        const float* __restrict__ g2, const float* __restrict__ gb2) {
    int t = threadIdx.x;
    if (t < 64) {
        float s1 = g_stats[2 * t], s2 = g_stats[2 * t + 1];
        float invN = 1.f / (16.f * (float)PP);
        float mu = s1 * invN;
        float var = s2 * invN - mu * mu;
        g_munorm[2 * t] = mu;
        g_munorm[2 * t + 1] = rsqrtf(var + 1e-5f);
    }
    __shared__ float sh[8][16];
    int w = t >> 5, lane = t & 31;
    const float invHW = 1.f / (float)HWSZ;
    if (lane < 16) {
        float s = gb1[lane];
        #pragma unroll 4
        for (int c = 0; c < 64; c++) s += (g_density[w * 64 + c] * invHW) * g1[lane * 64 + c];
        sh[w][lane] = fmaxf(s, 0.f);
    }
    __syncwarp();
    if (lane < 4) {
        float s = gb2[lane];
        #pragma unroll
        for (int i = 0; i < 16; i++) s += sh[w][i] * g2[lane * 16 + i];
        g_gates[w * 4 + lane] = 1.f / (1.f + expf(-s));
    }
}

// ---------------- K5: gemm2 (fp16 mma + ldmatrix) ----------------
__global__ void __launch_bounds__(256) k_gemm2(const float* __restrict__ b2,
                                               const float* __restrict__ gamma,
                                               const float* __restrict__ beta) {
    const int b = blockIdx.y;
    const int p0 = blockIdx.x * 64;
    __shared__ __half sW[2][256][24];
    __shared__ __half sA[2][16][72];
    __shared__ float sScale[128], sShift[128];
    const int tid = threadIdx.x;
    if (tid < 128) {
        int qq = tid, g = qq >> 4;
        float mu = g_munorm[(b * 8 + g) * 2];
        float rs = g_munorm[(b * 8 + g) * 2 + 1];
        float sc = rs * gamma[qq];
        sScale[qq] = sc;
        sShift[qq] = beta[qq] - mu * sc;
    }
    __syncthreads();
    const int w = tid >> 5, lane = tid & 31;
    const int gid = lane >> 2, tig = lane & 3;
    const int obase = (w >> 1) * 64, pbase = (w & 1) * 32;
    float4 acc[4][4] = {};
    const float* zb = g_z + (size_t)b * 128 * PSTR;
    const bool fullA = (p0 + 64 <= PP);

    const int ar = tid >> 4, ac = (tid & 15) * 4;   // A: 16 k-rows x 64 px
    float4 ra; uint4 rw0v, rw1v;

    #define G2_LOAD(qc) do { \
        if (fullA) { \
            ra = *(const float4*)&zb[(size_t)((qc) + ar) * PSTR + p0 + ac]; \
        } else { \
            const float* rp = &zb[(size_t)((qc) + ar) * PSTR]; \
            ra.x = (p0+ac   < PP) ? rp[p0+ac]   : 0.f; \
            ra.y = (p0+ac+1 < PP) ? rp[p0+ac+1] : 0.f; \
            ra.z = (p0+ac+2 < PP) ? rp[p0+ac+2] : 0.f; \
            ra.w = (p0+ac+3 < PP) ? rp[p0+ac+3] : 0.f; \
        } \
        rw0v = *(const uint4*)&g_w2h[tid * 128 + (qc)]; \
        rw1v = *(const uint4*)&g_w2h[tid * 128 + (qc) + 8]; \
    } while (0)
    #define G2_GELU(v, row) do { \
        float sc_ = sScale[row], sh_ = sShift[row]; \
        v.x = v.x * sc_ + sh_; v.x = 0.5f * v.x * (1.f + erff(v.x * 0.70710678118654752f)); \
        v.y = v.y * sc_ + sh_; v.y = 0.5f * v.y * (1.f + erff(v.y * 0.70710678118654752f)); \
        v.z = v.z * sc_ + sh_; v.z = 0.5f * v.z * (1.f + erff(v.z * 0.70710678118654752f)); \
        v.w = v.w * sc_ + sh_; v.w = 0.5f * v.w * (1.f + erff(v.w * 0.70710678118654752f)); \
    } while (0)
    #define G2_STORE(st, qc) do { \
        G2_GELU(ra, (qc) + ar); \
        uint2 pk; pk.x = packh2(ra.x, ra.y); pk.y = packh2(ra.z, ra.w); \
        *(uint2*)&sA[st][ar][ac] = pk; \
        *(uint4*)&sW[st][tid][0] = rw0v; \
        *(uint4*)&sW[st][tid][8] = rw1v; \
    } while (0)

    uint32_t saddrA = (uint32_t)__cvta_generic_to_shared(&sA[0][0][0]);
    uint32_t saddrW = (uint32_t)__cvta_generic_to_shared(&sW[0][0][0]);
    const int q = lane >> 3, r = lane & 7;
    const uint32_t aoff = (uint32_t)((((q & 1) * 8 + r) * 72 + (q >> 1) * 8) * 2);
    uint32_t woff[4];
    #pragma unroll
    for (int mt = 0; mt < 4; mt++)
        woff[mt] = (uint32_t)(((obase + mt * 16 + (q & 1) * 8 + r) * 24 + (q >> 1) * 8) * 2);

    G2_LOAD(0); G2_STORE(0, 0);
    __syncthreads();
    int cur = 0;
    for (int qc = 0; qc < 128; qc += 16) {
        const bool hasnext = (qc + 16 < 128);
        if (hasnext) G2_LOAD(qc + 16);
        uint32_t baA = saddrA + (uint32_t)(cur * 16 * 72 * 2);
        uint32_t baW = saddrW + (uint32_t)(cur * 256 * 24 * 2);
        uint32_t wa[4][4];
        #pragma unroll
        for (int mt = 0; mt < 4; mt++) ldsm4(wa[mt], baW + woff[mt]);
        #pragma unroll
        for (int j = 0; j < 2; j++) {
            uint32_t ab[4];
            ldsm4t(ab, baA + aoff + (uint32_t)((pbase + j * 16) * 2));
            #pragma unroll
            for (int mt = 0; mt < 4; mt++) {
                mma_f16(acc[mt][2 * j],     wa[mt], ab[0], ab[1]);
                mma_f16(acc[mt][2 * j + 1], wa[mt], ab[2], ab[3]);
            }
        }
        if (hasnext) G2_STORE(cur ^ 1, qc + 16);
        __syncthreads();
        cur ^= 1;
    }
    __half* gbuf = g_ffh + (size_t)b * 256 * PSTRH;
    #pragma unroll
    for (int mt = 0; mt < 4; mt++) {
        int o1 = obase + mt * 16 + gid;
        float ga = g_gates[b * 4 + (o1 >> 6)];
        float gb_ = g_gates[b * 4 + ((o1 + 8) >> 6)];
        float bia = b2[o1], bib = b2[o1 + 8];
        #pragma unroll
        for (int nt = 0; nt < 4; nt++) {
            int p = p0 + pbase + nt * 8 + 2 * tig;
            float vx = (acc[mt][nt].x + bia) * ga, vy = (acc[mt][nt].y + bia) * ga;
            float vz = (acc[mt][nt].z + bib) * gb_, vw = (acc[mt][nt].w + bib) * gb_;
            if (fullA) {
                *(__half2*)&gbuf[(size_t)o1 * PSTRH + p] = __floats2half2_rn(vx, vy);
                *(__half2*)&gbuf[(size_t)(o1 + 8) * PSTRH + p] = __floats2half2_rn(vz, vw);
            } else {
                if (p < PP)     { gbuf[(size_t)o1*PSTRH + p] = __float2half_rn(vx);     gbuf[(size_t)(o1+8)*PSTRH + p] = __float2half_rn(vz); }
                if (p + 1 < PP) { gbuf[(size_t)o1*PSTRH + p + 1] = __float2half_rn(vy); gbuf[(size_t)(o1+8)*PSTRH + p + 1] = __float2half_rn(vw); }
            }
        }
    }
}

// ---------------- K6: IDWT2 -> g_reconh (fp16 out) ----------------
__global__ void __launch_bounds__(256) k_idwt() {
    int tile = blockIdx.x;
    int bc = blockIdx.y;
    int h0 = (tile >> 2) * 32;
    int w0 = (tile & 3) * 64;
    int b = bc >> 6, c = bc & 63;
    __shared__ float scoef[4][19][36];
    __shared__ float stmp[4][19][68];
    const __half* gb = g_ffh + ((size_t)b * 256 + c) * PSTRH;
    int ib0 = h0 >> 1, jb0 = w0 >> 1;

    for (int idx = threadIdx.x; idx < 4 * 19 * 35; idx += 256) {
        int k = idx / (19 * 35); int rem = idx % (19 * 35);
        int il = rem / 35, jl = rem % 35;
        scoef[k][il][jl] = __half2float(gb[(size_t)k * 64 * PSTRH + (ib0 + il) * OWW + jb0 + jl]);
    }
    __syncthreads();
    for (int s = threadIdx.x; s < 19 * 16; s += 256) {
        int il = s >> 4, ws = s & 15;
        int wl = ws * 4, jb = wl >> 1;
        #pragma unroll
        for (int k = 0; k < 4; k++) {
            const float* fc = (k < 2) ? DEC_LO : DEC_HI;
            float c0 = scoef[k][il][jb],     c1 = scoef[k][il][jb + 1];
            float c2 = scoef[k][il][jb + 2], c3 = scoef[k][il][jb + 3];
            float c4 = scoef[k][il][jb + 4];
            stmp[k][il][wl + 0] = c0*fc[1] + c1*fc[3] + c2*fc[5] + c3*fc[7];
            stmp[k][il][wl + 1] = c0*fc[0] + c1*fc[2] + c2*fc[4] + c3*fc[6];
            stmp[k][il][wl + 2] = c1*fc[1] + c2*fc[3] + c3*fc[5] + c4*fc[7];
            stmp[k][il][wl + 3] = c1*fc[0] + c2*fc[2] + c3*fc[4] + c4*fc[6];
        }
    }
    __syncthreads();
    __half* rb = g_reconh + ((size_t)b * 64 + c) * HWSZ;
    for (int s = threadIdx.x; s < 512; s += 256) {
        int wlh = s & 63, hs = s >> 6;
        int hb = hs * 4, ib = hb >> 1;
        float t[4][5];
        #pragma unroll
        for (int k = 0; k < 4; k++)
            #pragma unroll
            for (int m = 0; m < 5; m++)
                t[k][m] = stmp[k][ib + m][wlh];
        #pragma unroll
        for (int dh = 0; dh < 4; dh++) {
            int sh = dh >> 1;
            float acc = 0.f;
            #pragma unroll
            for (int k = 0; k < 4; k++) {
                const float* fr = (k & 1) ? DEC_HI : DEC_LO;
                if (dh & 1)
                    acc += t[k][sh]*fr[0] + t[k][sh+1]*fr[2] + t[k][sh+2]*fr[4] + t[k][sh+3]*fr[6];
                else
                    acc += t[k][sh]*fr[1] + t[k][sh+1]*fr[3] + t[k][sh+2]*fr[5] + t[k][sh+3]*fr[7];
            }
            rb[(h0 + hb + dh) * WW + w0 + wlh] = __float2half(acc);
        }
    }
}

// ---------------- K7: fused = [x, recon] @ wf^T + bf (fp16 mma) ----------------
__global__ void __launch_bounds__(256) k_final(const float* __restrict__ x,
                                               const float* __restrict__ bf,
                                               float* __restrict__ out) {
    const int b = blockIdx.y;
    const int p0 = blockIdx.x * 256;
    __shared__ __half sW[2][64][24];
    __shared__ __half sA[2][16][264];
    const int tid = threadIdx.x;
    const int w = tid >> 5, lane = tid & 31;
    const int gid = lane >> 2, tig = lane & 3;
    const int obase = (w >> 2) * 32, pbase = (w & 3) * 64;
    float4 acc[2][8] = {};
    const float* xb = x + (size_t)b * 64 * HWSZ;
    const __half* rbh = g_reconh + (size_t)b * 64 * HWSZ;

    // A fill: 2 items of 8 px each. row = ch-in-tile, cb = px block
    const int row0 = tid >> 5, cb0 = (tid & 31) * 8;
    const int wo0 = tid >> 1, wk8 = (tid & 1) * 8;  // 128 threads for W
    uint4 ra[2]; uint4 rwv;

    #define G3_LOAD(cc) do { \
        _Pragma("unroll") \
        for (int s = 0; s < 2; s++) { \
            int row = row0 + s * 8; \
            int ch = (cc) + row; \
            if (ch < 64) { \
                const float* src = &xb[(size_t)ch * HWSZ + p0 + cb0]; \
                float4 v0 = *(const float4*)src; \
                float4 v1 = *(const float4*)(src + 4); \
                ra[s].x = packh2(v0.x, v0.y); ra[s].y = packh2(v0.z, v0.w); \
                ra[s].z = packh2(v1.x, v1.y); ra[s].w = packh2(v1.z, v1.w); \
            } else { \
                ra[s] = *(const uint4*)&rbh[(size_t)(ch - 64) * HWSZ + p0 + cb0]; \
            } \
        } \
        if (tid < 128) rwv = *(const uint4*)&g_wfh[wo0 * 128 + (cc) + wk8]; \
    } while (0)
    #define G3_STORE(st) do { \
        _Pragma("unroll") \
        for (int s = 0; s < 2; s++) \
            *(uint4*)&sA[st][row0 + s * 8][cb0] = ra[s]; \
        if (tid < 128) *(uint4*)&sW[st][wo0][wk8] = rwv; \
    } while (0)

    uint32_t saddrA = (uint32_t)__cvta_generic_to_shared(&sA[0][0][0]);
    uint32_t saddrW = (uint32_t)__cvta_generic_to_shared(&sW[0][0][0]);
    const int q = lane >> 3, r = lane & 7;
    const uint32_t aoff = (uint32_t)((((q & 1) * 8 + r) * 264 + (q >> 1) * 8) * 2);
    const uint32_t woff0 = (uint32_t)(((obase + (q & 1) * 8 + r) * 24 + (q >> 1) * 8) * 2);
    const uint32_t woff1 = woff0 + 16 * 24 * 2;

    G3_LOAD(0); G3_STORE(0);
    __syncthreads();
    int cur = 0;
    for (int cc = 0; cc < 128; cc += 16) {
        const bool hasnext = (cc + 16 < 128);
        if (hasnext) G3_LOAD(cc + 16);
        uint32_t baA = saddrA + (uint32_t)(cur * 16 * 264 * 2);
        uint32_t baW = saddrW + (uint32_t)(cur * 64 * 24 * 2);
        uint32_t wa0[4], wa1[4];
        ldsm4(wa0, baW + woff0);
        ldsm4(wa1, baW + woff1);
        #pragma unroll
        for (int j = 0; j < 4; j++) {
            uint32_t ab[4];
            ldsm4t(ab, baA + aoff + (uint32_t)((pbase + j * 16) * 2));
            mma_f16(acc[0][2 * j],     wa0, ab[0], ab[1]);
            mma_f16(acc[1][2 * j],     wa1, ab[0], ab[1]);
            mma_f16(acc[0][2 * j + 1], wa0, ab[2], ab[3]);
            mma_f16(acc[1][2 * j + 1], wa1, ab[2], ab[3]);
        }
        if (hasnext) G3_STORE(cur ^ 1);
        __syncthreads();
        cur ^= 1;
    }
    float* ob = out + (size_t)b * 64 * HWSZ;
    #pragma unroll
    for (int mt = 0; mt < 2; mt++) {
        int o1 = obase + mt * 16 + gid;
        float bia = bf[o1], bib = bf[o1 + 8];
        #pragma unroll
        for (int nt = 0; nt < 8; nt++) {
            int p = p0 + pbase + nt * 8 + 2 * tig;
            *(float2*)&ob[(size_t)o1 * HWSZ + p] = make_float2(acc[mt][nt].x + bia, acc[mt][nt].y + bia);
            *(float2*)&ob[(size_t)(o1 + 8) * HWSZ + p] = make_float2(acc[mt][nt].z + bib, acc[mt][nt].w + bib);
        }
    }
}

extern "C" void kernel_launch(void* const* d_in, const int* in_sizes, int n_in,
                              void* d_out, int out_size) {
    const float* x     = (const float*)d_in[0];
    const float* w1    = (const float*)d_in[1];
    const float* b1    = (const float*)d_in[2];
    const float* gamma = (const float*)d_in[3];
    const float* beta  = (const float*)d_in[4];
    const float* w2    = (const float*)d_in[5];
    const float* b2    = (const float*)d_in[6];
    const float* g1    = (const float*)d_in[7];
    const float* gb1   = (const float*)d_in[8];
    const float* g2    = (const float*)d_in[9];
    const float* gb2   = (const float*)d_in[10];
    const float* wf    = (const float*)d_in[11];
    const float* bf    = (const float*)d_in[12];
    float* out = (float*)d_out;

    // launch order: k_gemm1 sits at profiled launch index 3
    k_prep<<<128, 256>>>(w1, w2, wf, 0);
    k_prep<<<128, 256>>>(w1, w2, wf, 1);
    k_dwt<<<dim3(17, 512), 256>>>(x);
    k_gemm1<<<dim3(135, 8), 256>>>(b1);
    k_small<<<1, 256>>>(g1, gb1, g2, gb2);
    k_gemm2<<<dim3(269, 8), 256>>>(b2, gamma, beta);
    k_idwt<<<dim3(32, 512), 256>>>();
    k_final<<<dim3(256, 8), 256>>>(x, bf, out);
}